// round 1
// baseline (speedup 1.0000x reference)
#include <cuda_runtime.h>
#include <math.h>

#define NN 10000
#define HH 64
#define EE 40000
#define MD 12

// ---------------- scratch (device globals; no allocation) ----------------
__device__ int   g_deg[4*NN];
__device__ int   g_start[4*NN];
__device__ int   g_cur[4*NN];
__device__ int   g_csr[4*EE];
__device__ int   g_nbr[4*NN*MD];
__device__ float g_sb[2][NN*HH];
__device__ float g_tb[2][NN*HH];
__device__ float g_agg[4][NN*HH];
__device__ float g_U[(NN+1)*256];
__device__ float g_Wp[12*64*256];   // permuted Whh: [blk][k][p]

// gate-permuted index: p -> row of Wih/Whh (torch gate order i,f,g,o)
// p = q*128 + lane*4 + gate, with d = 2*lane + q, row = gate*64 + d
__device__ __forceinline__ int pmap_row(int p){
    return (p & 3) * 64 + 2 * ((p >> 2) & 31) + (p >> 7);
}
__device__ __forceinline__ float sigf(float x){ return 1.0f/(1.0f + __expf(-x)); }
__device__ __forceinline__ float tanh_(float x){
    float e = __expf(-2.0f * fabsf(x));
    float t = (1.0f - e) / (1.0f + e);
    return copysignf(t, x);
}

// ---------------- graph preprocessing ----------------
__global__ void k_zero(){
    int i = blockIdx.x*blockDim.x + threadIdx.x;
    if(i < 4*NN){ g_deg[i] = 0; g_cur[i] = 0; }
}

__global__ void k_degree(const int* __restrict__ edges){
    int i = blockIdx.x*blockDim.x + threadIdx.x;
    if(i >= 4*EE) return;
    int t = i / EE, e = i - t*EE;
    int dst = edges[t*2*EE + EE + e];
    atomicAdd(&g_deg[t*NN + dst], 1);
}

__global__ void k_scan(){
    __shared__ int sm[1024];
    int t = blockIdx.x, tid = threadIdx.x;
    const int CH = 10;                       // 1024*10 >= 10000
    int loc[CH]; int s = 0;
    int base = tid * CH;
    #pragma unroll
    for(int c=0;c<CH;c++){ int i = base + c; int v = (i<NN) ? g_deg[t*NN+i] : 0; loc[c] = v; s += v; }
    sm[tid] = s; __syncthreads();
    for(int off=1; off<1024; off<<=1){
        int v = (tid >= off) ? sm[tid-off] : 0;
        __syncthreads();
        sm[tid] += v;
        __syncthreads();
    }
    int run = sm[tid] - s;                   // exclusive prefix
    #pragma unroll
    for(int c=0;c<CH;c++){ int i = base + c; if(i < NN){ g_start[t*NN+i] = run; run += loc[c]; } }
}

__global__ void k_scatter(const int* __restrict__ edges){
    int i = blockIdx.x*blockDim.x + threadIdx.x;
    if(i >= 4*EE) return;
    int t = i / EE, e = i - t*EE;
    int src = edges[t*2*EE + e];
    int dst = edges[t*2*EE + EE + e];
    int p = atomicAdd(&g_cur[t*NN + dst], 1);
    g_csr[t*EE + g_start[t*NN + dst] + p] = src;
}

// top-12 smallest src per dst (incl. self loop), pad with sentinel NN
__global__ void k_buildnbr(){
    int i = blockIdx.x*blockDim.x + threadIdx.x;
    if(i >= 4*NN) return;
    int t = i / NN, n = i - t*NN;
    int arr[MD];
    #pragma unroll
    for(int k=0;k<MD;k++) arr[k] = 0x7fffffff;
    arr[0] = n;                              // self loop
    int st = g_start[t*NN + n], d = g_deg[t*NN + n];
    for(int q=0;q<d;q++){
        int v = g_csr[t*EE + st + q];
        if(v < arr[MD-1]){
            int j = MD-1;
            while(j > 0 && arr[j-1] > v){ arr[j] = arr[j-1]; j--; }
            arr[j] = v;
        }
    }
    int cnt = d + 1; if(cnt > MD) cnt = MD;
    #pragma unroll
    for(int k=0;k<MD;k++) g_nbr[i*MD + k] = (k < cnt) ? arr[k] : NN;
}

__global__ void k_wperm(const float* __restrict__ Whh){
    int idx = blockIdx.x*blockDim.x + threadIdx.x;
    if(idx >= 12*16384) return;
    int i = idx >> 14; int r = idx & 16383; int k = r >> 8; int p = r & 255;
    g_Wp[idx] = Whh[i*16384 + pmap_row(p)*64 + k];
}

// ---------------- node encoder (Linear-ReLU-Linear) ----------------
__global__ void k_enc(const float* __restrict__ x, int K,
                      const float* __restrict__ W1, const float* __restrict__ b1,
                      const float* __restrict__ W2, const float* __restrict__ b2,
                      int isT){
    __shared__ float xr[32];
    __shared__ float hid[64];
    int n = blockIdx.x, j = threadIdx.x;
    if(j < K) xr[j] = x[n*K + j];
    __syncthreads();
    float a = __ldg(&b1[j]);
    for(int k=0;k<K;k++) a = fmaf(xr[k], __ldg(&W1[j*K + k]), a);
    hid[j] = fmaxf(a, 0.0f);
    __syncthreads();
    float b = __ldg(&b2[j]);
    #pragma unroll 8
    for(int k=0;k<64;k++) b = fmaf(hid[k], __ldg(&W2[j*64 + k]), b);
    float* out = isT ? g_tb[0] : g_sb[0];
    out[n*64 + j] = b;
}

// ---------------- U = X @ Wih^T + bih + bhh (gate-permuted), row NN = bias only ----
__global__ void k_U(const float* __restrict__ Wih, const float* __restrict__ bih,
                    const float* __restrict__ bhh, int blk, int isT, int inSel){
    const float* x = isT ? g_tb[inSel] : g_sb[inSel];
    __shared__ float4 xsm[64*16];
    int p = threadIdx.x;
    int row = pmap_row(p);
    float bias = __ldg(&bih[blk*256 + row]) + __ldg(&bhh[blk*256 + row]);
    float4 w[16];
    const float4* wsrc = (const float4*)(Wih + (size_t)blk*16384 + row*64);
    #pragma unroll
    for(int q=0;q<16;q++) w[q] = __ldg(&wsrc[q]);
    int nb = blockIdx.x * 64;
    #pragma unroll
    for(int r=0;r<4;r++){
        int idx = p + r*256;
        int node = nb + (idx >> 4);
        float4 v = make_float4(0,0,0,0);
        if(node < NN) v = ((const float4*)x)[node*16 + (idx & 15)];
        xsm[idx] = v;
    }
    __syncthreads();
    for(int m=0;m<64;m++){
        int node = nb + m;
        if(node > NN) return;
        float acc = bias;
        #pragma unroll
        for(int q=0;q<16;q++){
            float4 xv = xsm[m*16 + q];
            acc = fmaf(xv.x, w[q].x, acc);
            acc = fmaf(xv.y, w[q].y, acc);
            acc = fmaf(xv.z, w[q].z, acc);
            acc = fmaf(xv.w, w[q].w, acc);
        }
        g_U[node*256 + p] = acc;
    }
}

// ---------------- LSTM aggregation (hot kernel) ----------------
// 1 warp = 4 nodes; Whh (permuted) in smem; h in smem; c + gates in registers.
__global__ void k_lstm(int blk, int et){
    extern __shared__ float smem[];
    float* Wsm = smem;                        // 16384 floats
    float* hsm = smem + 16384;                // 32*64 floats
    int tid = threadIdx.x;
    const float4* wp = (const float4*)(g_Wp + blk*16384);
    float4* Wsm4 = (float4*)Wsm;
    #pragma unroll
    for(int r=0;r<16;r++) Wsm4[tid + r*256] = wp[tid + r*256];
    #pragma unroll
    for(int r=0;r<8;r++) hsm[tid + r*256] = 0.0f;
    __syncthreads();

    int warp = tid >> 5, lane = tid & 31;
    int nbase = blockIdx.x*32 + warp*4;
    const int* nbr = g_nbr + et*NN*MD;
    float c0[4], c1[4], h0[4], h1[4];
    int nodes[4];
    float* hrow[4];
    #pragma unroll
    for(int m=0;m<4;m++){
        c0[m]=0; c1[m]=0; h0[m]=0; h1[m]=0;
        int n = nbase + m; nodes[m] = (n < NN) ? n : NN-1;
        hrow[m] = &hsm[(warp*4 + m)*64];
    }
    const float4* U4 = (const float4*)g_U;

    for(int t=0;t<MD;t++){
        float acc[4][8];
        #pragma unroll
        for(int m=0;m<4;m++){
            int nb = __ldg(&nbr[nodes[m]*MD + t]);
            float4 a0 = __ldg(&U4[nb*64 + lane]);
            float4 a1 = __ldg(&U4[nb*64 + 32 + lane]);
            acc[m][0]=a0.x; acc[m][1]=a0.y; acc[m][2]=a0.z; acc[m][3]=a0.w;
            acc[m][4]=a1.x; acc[m][5]=a1.y; acc[m][6]=a1.z; acc[m][7]=a1.w;
        }
        #pragma unroll 4
        for(int k0=0;k0<64;k0+=4){
            float4 h4[4];
            #pragma unroll
            for(int m=0;m<4;m++) h4[m] = *(const float4*)&hrow[m][k0];
            #pragma unroll
            for(int dk=0;dk<4;dk++){
                int k = k0 + dk;
                float4 wa = Wsm4[k*64 + lane];
                float4 wb = Wsm4[k*64 + 32 + lane];
                #pragma unroll
                for(int m=0;m<4;m++){
                    float hv = (dk==0)?h4[m].x:(dk==1)?h4[m].y:(dk==2)?h4[m].z:h4[m].w;
                    acc[m][0]=fmaf(hv,wa.x,acc[m][0]);
                    acc[m][1]=fmaf(hv,wa.y,acc[m][1]);
                    acc[m][2]=fmaf(hv,wa.z,acc[m][2]);
                    acc[m][3]=fmaf(hv,wa.w,acc[m][3]);
                    acc[m][4]=fmaf(hv,wb.x,acc[m][4]);
                    acc[m][5]=fmaf(hv,wb.y,acc[m][5]);
                    acc[m][6]=fmaf(hv,wb.z,acc[m][6]);
                    acc[m][7]=fmaf(hv,wb.w,acc[m][7]);
                }
            }
        }
        __syncwarp();
        #pragma unroll
        for(int m=0;m<4;m++){
            float ig=sigf(acc[m][0]), fg=sigf(acc[m][1]);
            float gg=tanh_(acc[m][2]), og=sigf(acc[m][3]);
            c0[m] = fg*c0[m] + ig*gg;
            h0[m] = og*tanh_(c0[m]);
            float ig2=sigf(acc[m][4]), fg2=sigf(acc[m][5]);
            float gg2=tanh_(acc[m][6]), og2=sigf(acc[m][7]);
            c1[m] = fg2*c1[m] + ig2*gg2;
            h1[m] = og2*tanh_(c1[m]);
            ((float2*)hrow[m])[lane] = make_float2(h0[m], h1[m]);
        }
        __syncwarp();
    }
    float* agg = g_agg[et];
    #pragma unroll
    for(int m=0;m<4;m++){
        int n = nbase + m;
        if(n < NN) ((float2*)(agg + n*64))[lane] = make_float2(h0[m], h1[m]);
    }
}

// ---------------- per-layer combine: SAGE linear + hetero-mean + relu (+res) ----
__global__ void k_comb(const float* __restrict__ Wl, const float* __restrict__ bl,
                       const float* __restrict__ Wr,
                       int ia, int ib, int etA, int etB,
                       int inSel, int outSel, int isT, int useRes){
    __shared__ float A[64], B[64], X[64];
    int n = blockIdx.x, j = threadIdx.x;
    const float* xin = isT ? g_tb[inSel] : g_sb[inSel];
    float* out = isT ? g_tb[outSel] : g_sb[outSel];
    A[j] = g_agg[etA][n*64 + j];
    B[j] = g_agg[etB][n*64 + j];
    X[j] = xin[n*64 + j];
    __syncthreads();
    const float* WlA = Wl + ia*4096; const float* WlB = Wl + ib*4096;
    const float* WrA = Wr + ia*4096; const float* WrB = Wr + ib*4096;
    float acc = __ldg(&bl[ia*64 + j]) + __ldg(&bl[ib*64 + j]);
    #pragma unroll 4
    for(int k=0;k<64;k++){
        acc = fmaf(A[k], __ldg(&WlA[j*64 + k]), acc);
        acc = fmaf(B[k], __ldg(&WlB[j*64 + k]), acc);
        acc = fmaf(X[k], __ldg(&WrA[j*64 + k]) + __ldg(&WrB[j*64 + k]), acc);
    }
    acc *= 0.5f;
    if(useRes) acc += X[j];
    out[n*64 + j] = fmaxf(acc, 0.0f);
}

// ---------------- edge head ----------------
__global__ void k_edge(const int* __restrict__ edges, const float* __restrict__ ea,
    const float* __restrict__ Wg1, const float* __restrict__ bg1,
    const float* __restrict__ Wg2, const float* __restrict__ bg2,
    const float* __restrict__ Wm1, const float* __restrict__ bm1,
    const float* __restrict__ Wm2, const float* __restrict__ bm2,
    const float* __restrict__ Wm3, const float* __restrict__ bm3,
    float* __restrict__ out){
    __shared__ float se[64], te[64], cat2[80], h1s[64], h2s[32], red[64];
    __shared__ float gsh;
    int e = blockIdx.x, j = threadIdx.x;
    int s = edges[4*EE + e];     // et=2 src
    int t = edges[5*EE + e];     // et=2 dst
    se[j] = g_sb[1][s*64 + j];
    te[j] = g_tb[1][t*64 + j];
    __syncthreads();
    float a = __ldg(&bg1[j]);
    #pragma unroll 4
    for(int k=0;k<64;k++) a = fmaf(se[k], __ldg(&Wg1[j*128 + k]), a);
    #pragma unroll 4
    for(int k=0;k<64;k++) a = fmaf(te[k], __ldg(&Wg1[j*128 + 64 + k]), a);
    a = fmaxf(a, 0.0f);
    red[j] = a * __ldg(&Wg2[j]);
    __syncthreads();
    if(j<32) red[j] += red[j+32]; __syncthreads();
    if(j<16) red[j] += red[j+16]; __syncthreads();
    if(j<8)  red[j] += red[j+8];  __syncthreads();
    if(j<4)  red[j] += red[j+4];  __syncthreads();
    if(j<2)  red[j] += red[j+2];  __syncthreads();
    if(j==0) gsh = sigf(red[0] + red[1] + __ldg(&bg2[0]));
    __syncthreads();
    float g = gsh;
    cat2[j] = g*se[j] + (1.0f - g)*te[j];
    if(j < 16) cat2[64 + j] = ea[e*16 + j];
    __syncthreads();
    float m = __ldg(&bm1[j]);
    #pragma unroll 4
    for(int k=0;k<80;k++) m = fmaf(cat2[k], __ldg(&Wm1[j*80 + k]), m);
    h1s[j] = fmaxf(m, 0.0f);
    __syncthreads();
    if(j < 32){
        float m2 = __ldg(&bm2[j]);
        #pragma unroll 4
        for(int k=0;k<64;k++) m2 = fmaf(h1s[k], __ldg(&Wm2[j*64 + k]), m2);
        h2s[j] = fmaxf(m2, 0.0f);
    }
    __syncthreads();
    if(j < 2){
        float o = __ldg(&bm3[j]);
        #pragma unroll
        for(int k=0;k<32;k++) o = fmaf(h2s[k], __ldg(&Wm3[j*32 + k]), o);
        out[e*2 + j] = o;
    }
}

// ---------------- host launcher ----------------
extern "C" void kernel_launch(void* const* d_in, const int* in_sizes, int n_in,
                              void* d_out, int out_size){
    const float* x_source = (const float*)d_in[0];
    const float* x_target = (const float*)d_in[1];
    const int*   edges    = (const int*)  d_in[2];
    const float* ea       = (const float*)d_in[3];
    const float* We_s1=(const float*)d_in[4];  const float* be_s1=(const float*)d_in[5];
    const float* We_s2=(const float*)d_in[6];  const float* be_s2=(const float*)d_in[7];
    const float* We_t1=(const float*)d_in[8];  const float* be_t1=(const float*)d_in[9];
    const float* We_t2=(const float*)d_in[10]; const float* be_t2=(const float*)d_in[11];
    const float* Wih=(const float*)d_in[12];   const float* Whh=(const float*)d_in[13];
    const float* bih=(const float*)d_in[14];   const float* bhh=(const float*)d_in[15];
    const float* Wl =(const float*)d_in[16];   const float* bl =(const float*)d_in[17];
    const float* Wr =(const float*)d_in[18];
    const float* Wg1=(const float*)d_in[19];   const float* bg1=(const float*)d_in[20];
    const float* Wg2=(const float*)d_in[21];   const float* bg2=(const float*)d_in[22];
    const float* Wm1=(const float*)d_in[23];   const float* bm1=(const float*)d_in[24];
    const float* Wm2=(const float*)d_in[25];   const float* bm2=(const float*)d_in[26];
    const float* Wm3=(const float*)d_in[27];   const float* bm3=(const float*)d_in[28];
    float* out = (float*)d_out;

    cudaFuncSetAttribute(k_lstm, cudaFuncAttributeMaxDynamicSharedMemorySize, 73728);

    k_zero    <<<(4*NN+255)/256, 256>>>();
    k_degree  <<<(4*EE+255)/256, 256>>>(edges);
    k_scan    <<<4, 1024>>>();
    k_scatter <<<(4*EE+255)/256, 256>>>(edges);
    k_buildnbr<<<(4*NN+127)/128, 128>>>();
    k_wperm   <<<(12*16384+255)/256, 256>>>(Whh);
    k_enc     <<<NN, 64>>>(x_source, 32, We_s1, be_s1, We_s2, be_s2, 0);
    k_enc     <<<NN, 64>>>(x_target, 24, We_t1, be_t1, We_t2, be_t2, 1);

    for(int L=0; L<3; L++){
        int in = L & 1, o = 1 - in;
        for(int et=0; et<4; et++){
            int i = L*4 + et;
            int srcIsT = (et==1 || et==3);
            k_U   <<<157, 256>>>(Wih, bih, bhh, i, srcIsT, in);
            k_lstm<<<313, 256, 73728>>>(i, et);
        }
        k_comb<<<NN, 64>>>(Wl, bl, Wr, L*4+0, L*4+3, 0, 3, in, o, 0, (L>0)?1:0);
        k_comb<<<NN, 64>>>(Wl, bl, Wr, L*4+1, L*4+2, 1, 2, in, o, 1, (L>0)?1:0);
    }
    k_edge<<<EE, 64>>>(edges, ea, Wg1, bg1, Wg2, bg2, Wm1, bm1, Wm2, bm2, Wm3, bm3, out);
}

// round 2
// speedup vs baseline: 1.0006x; 1.0006x over previous
#include <cuda_runtime.h>
#include <math.h>

#define NN 10000
#define HH 64
#define EE 40000
#define MD 12

// ---------------- scratch (device globals; no allocation) ----------------
__device__ int   g_deg[4*NN];
__device__ int   g_start[4*NN];
__device__ int   g_cur[4*NN];
__device__ int   g_csr[4*EE];
__device__ int   g_nbr[4*NN*MD];
__device__ float g_sb[2][NN*HH];
__device__ float g_tb[2][NN*HH];
__device__ float g_agg[4][NN*HH];
__device__ float g_U[(NN+1)*256];
__device__ float g_Wp[12*64*256];   // permuted Whh: [blk][k][p]

// gate-permuted index: p -> row of Wih/Whh (torch gate order i,f,g,o)
// p = q*128 + lane*4 + gate, with d = 2*lane + q, row = gate*64 + d
__device__ __forceinline__ int pmap_row(int p){
    return (p & 3) * 64 + 2 * ((p >> 2) & 31) + (p >> 7);
}
__device__ __forceinline__ float sigf(float x){ return 1.0f/(1.0f + __expf(-x)); }
__device__ __forceinline__ float tanh_(float x){
    float e = __expf(-2.0f * fabsf(x));
    float t = (1.0f - e) / (1.0f + e);
    return copysignf(t, x);
}

// ---------------- graph preprocessing ----------------
__global__ void k_zero(){
    int i = blockIdx.x*blockDim.x + threadIdx.x;
    if(i < 4*NN){ g_deg[i] = 0; g_cur[i] = 0; }
}

__global__ void k_degree(const int* __restrict__ edges){
    int i = blockIdx.x*blockDim.x + threadIdx.x;
    if(i >= 4*EE) return;
    int t = i / EE, e = i - t*EE;
    int dst = edges[t*2*EE + EE + e];
    atomicAdd(&g_deg[t*NN + dst], 1);
}

__global__ void k_scan(){
    __shared__ int sm[1024];
    int t = blockIdx.x, tid = threadIdx.x;
    const int CH = 10;                       // 1024*10 >= 10000
    int loc[CH]; int s = 0;
    int base = tid * CH;
    #pragma unroll
    for(int c=0;c<CH;c++){ int i = base + c; int v = (i<NN) ? g_deg[t*NN+i] : 0; loc[c] = v; s += v; }
    sm[tid] = s; __syncthreads();
    for(int off=1; off<1024; off<<=1){
        int v = (tid >= off) ? sm[tid-off] : 0;
        __syncthreads();
        sm[tid] += v;
        __syncthreads();
    }
    int run = sm[tid] - s;                   // exclusive prefix
    #pragma unroll
    for(int c=0;c<CH;c++){ int i = base + c; if(i < NN){ g_start[t*NN+i] = run; run += loc[c]; } }
}

__global__ void k_scatter(const int* __restrict__ edges){
    int i = blockIdx.x*blockDim.x + threadIdx.x;
    if(i >= 4*EE) return;
    int t = i / EE, e = i - t*EE;
    int src = edges[t*2*EE + e];
    int dst = edges[t*2*EE + EE + e];
    int p = atomicAdd(&g_cur[t*NN + dst], 1);
    g_csr[t*EE + g_start[t*NN + dst] + p] = src;
}

// top-12 smallest src per dst (incl. self loop), pad with sentinel NN
__global__ void k_buildnbr(){
    int i = blockIdx.x*blockDim.x + threadIdx.x;
    if(i >= 4*NN) return;
    int t = i / NN, n = i - t*NN;
    int arr[MD];
    #pragma unroll
    for(int k=0;k<MD;k++) arr[k] = 0x7fffffff;
    arr[0] = n;                              // self loop
    int st = g_start[t*NN + n], d = g_deg[t*NN + n];
    for(int q=0;q<d;q++){
        int v = g_csr[t*EE + st + q];
        if(v < arr[MD-1]){
            int j = MD-1;
            while(j > 0 && arr[j-1] > v){ arr[j] = arr[j-1]; j--; }
            arr[j] = v;
        }
    }
    int cnt = d + 1; if(cnt > MD) cnt = MD;
    #pragma unroll
    for(int k=0;k<MD;k++) g_nbr[i*MD + k] = (k < cnt) ? arr[k] : NN;
}

__global__ void k_wperm(const float* __restrict__ Whh){
    int idx = blockIdx.x*blockDim.x + threadIdx.x;
    if(idx >= 12*16384) return;
    int i = idx >> 14; int r = idx & 16383; int k = r >> 8; int p = r & 255;
    g_Wp[idx] = Whh[i*16384 + pmap_row(p)*64 + k];
}

// ---------------- node encoder (Linear-ReLU-Linear) ----------------
__global__ void k_enc(const float* __restrict__ x, int K,
                      const float* __restrict__ W1, const float* __restrict__ b1,
                      const float* __restrict__ W2, const float* __restrict__ b2,
                      int isT){
    __shared__ float xr[32];
    __shared__ float hid[64];
    int n = blockIdx.x, j = threadIdx.x;
    if(j < K) xr[j] = x[n*K + j];
    __syncthreads();
    float a = __ldg(&b1[j]);
    for(int k=0;k<K;k++) a = fmaf(xr[k], __ldg(&W1[j*K + k]), a);
    hid[j] = fmaxf(a, 0.0f);
    __syncthreads();
    float b = __ldg(&b2[j]);
    #pragma unroll 8
    for(int k=0;k<64;k++) b = fmaf(hid[k], __ldg(&W2[j*64 + k]), b);
    float* out = isT ? g_tb[0] : g_sb[0];
    out[n*64 + j] = b;
}

// ---------------- U = X @ Wih^T + bih + bhh (gate-permuted), row NN = bias only ----
__global__ void k_U(const float* __restrict__ Wih, const float* __restrict__ bih,
                    const float* __restrict__ bhh, int blk, int isT, int inSel){
    const float* x = isT ? g_tb[inSel] : g_sb[inSel];
    __shared__ float4 xsm[64*16];
    int p = threadIdx.x;
    int row = pmap_row(p);
    float bias = __ldg(&bih[blk*256 + row]) + __ldg(&bhh[blk*256 + row]);
    float4 w[16];
    const float4* wsrc = (const float4*)(Wih + (size_t)blk*16384 + row*64);
    #pragma unroll
    for(int q=0;q<16;q++) w[q] = __ldg(&wsrc[q]);
    int nb = blockIdx.x * 64;
    #pragma unroll
    for(int r=0;r<4;r++){
        int idx = p + r*256;
        int node = nb + (idx >> 4);
        float4 v = make_float4(0,0,0,0);
        if(node < NN) v = ((const float4*)x)[node*16 + (idx & 15)];
        xsm[idx] = v;
    }
    __syncthreads();
    for(int m=0;m<64;m++){
        int node = nb + m;
        if(node > NN) return;
        float acc = bias;
        #pragma unroll
        for(int q=0;q<16;q++){
            float4 xv = xsm[m*16 + q];
            acc = fmaf(xv.x, w[q].x, acc);
            acc = fmaf(xv.y, w[q].y, acc);
            acc = fmaf(xv.z, w[q].z, acc);
            acc = fmaf(xv.w, w[q].w, acc);
        }
        g_U[node*256 + p] = acc;
    }
}

// ---------------- LSTM aggregation (hot kernel) ----------------
// 1 warp = 4 nodes; Whh (permuted) in smem; h in smem; c + gates in registers.
__global__ void k_lstm(int blk, int et){
    extern __shared__ float smem[];
    float* Wsm = smem;                        // 16384 floats
    float* hsm = smem + 16384;                // 32*64 floats
    int tid = threadIdx.x;
    const float4* wp = (const float4*)(g_Wp + blk*16384);
    float4* Wsm4 = (float4*)Wsm;
    #pragma unroll
    for(int r=0;r<16;r++) Wsm4[tid + r*256] = wp[tid + r*256];
    #pragma unroll
    for(int r=0;r<8;r++) hsm[tid + r*256] = 0.0f;
    __syncthreads();

    int warp = tid >> 5, lane = tid & 31;
    int nbase = blockIdx.x*32 + warp*4;
    const int* nbr = g_nbr + et*NN*MD;
    float c0[4], c1[4], h0[4], h1[4];
    int nodes[4];
    float* hrow[4];
    #pragma unroll
    for(int m=0;m<4;m++){
        c0[m]=0; c1[m]=0; h0[m]=0; h1[m]=0;
        int n = nbase + m; nodes[m] = (n < NN) ? n : NN-1;
        hrow[m] = &hsm[(warp*4 + m)*64];
    }
    const float4* U4 = (const float4*)g_U;

    for(int t=0;t<MD;t++){
        float acc[4][8];
        #pragma unroll
        for(int m=0;m<4;m++){
            int nb = __ldg(&nbr[nodes[m]*MD + t]);
            float4 a0 = __ldg(&U4[nb*64 + lane]);
            float4 a1 = __ldg(&U4[nb*64 + 32 + lane]);
            acc[m][0]=a0.x; acc[m][1]=a0.y; acc[m][2]=a0.z; acc[m][3]=a0.w;
            acc[m][4]=a1.x; acc[m][5]=a1.y; acc[m][6]=a1.z; acc[m][7]=a1.w;
        }
        #pragma unroll 4
        for(int k0=0;k0<64;k0+=4){
            float4 h4[4];
            #pragma unroll
            for(int m=0;m<4;m++) h4[m] = *(const float4*)&hrow[m][k0];
            #pragma unroll
            for(int dk=0;dk<4;dk++){
                int k = k0 + dk;
                float4 wa = Wsm4[k*64 + lane];
                float4 wb = Wsm4[k*64 + 32 + lane];
                #pragma unroll
                for(int m=0;m<4;m++){
                    float hv = (dk==0)?h4[m].x:(dk==1)?h4[m].y:(dk==2)?h4[m].z:h4[m].w;
                    acc[m][0]=fmaf(hv,wa.x,acc[m][0]);
                    acc[m][1]=fmaf(hv,wa.y,acc[m][1]);
                    acc[m][2]=fmaf(hv,wa.z,acc[m][2]);
                    acc[m][3]=fmaf(hv,wa.w,acc[m][3]);
                    acc[m][4]=fmaf(hv,wb.x,acc[m][4]);
                    acc[m][5]=fmaf(hv,wb.y,acc[m][5]);
                    acc[m][6]=fmaf(hv,wb.z,acc[m][6]);
                    acc[m][7]=fmaf(hv,wb.w,acc[m][7]);
                }
            }
        }
        __syncwarp();
        #pragma unroll
        for(int m=0;m<4;m++){
            float ig=sigf(acc[m][0]), fg=sigf(acc[m][1]);
            float gg=tanh_(acc[m][2]), og=sigf(acc[m][3]);
            c0[m] = fg*c0[m] + ig*gg;
            h0[m] = og*tanh_(c0[m]);
            float ig2=sigf(acc[m][4]), fg2=sigf(acc[m][5]);
            float gg2=tanh_(acc[m][6]), og2=sigf(acc[m][7]);
            c1[m] = fg2*c1[m] + ig2*gg2;
            h1[m] = og2*tanh_(c1[m]);
            ((float2*)hrow[m])[lane] = make_float2(h0[m], h1[m]);
        }
        __syncwarp();
    }
    float* agg = g_agg[et];
    #pragma unroll
    for(int m=0;m<4;m++){
        int n = nbase + m;
        if(n < NN) ((float2*)(agg + n*64))[lane] = make_float2(h0[m], h1[m]);
    }
}

// ---------------- per-layer combine: SAGE linear + hetero-mean + relu (+res) ----
__global__ void k_comb(const float* __restrict__ Wl, const float* __restrict__ bl,
                       const float* __restrict__ Wr,
                       int ia, int ib, int etA, int etB,
                       int inSel, int outSel, int isT, int useRes){
    __shared__ float A[64], B[64], X[64];
    int n = blockIdx.x, j = threadIdx.x;
    const float* xin = isT ? g_tb[inSel] : g_sb[inSel];
    float* out = isT ? g_tb[outSel] : g_sb[outSel];
    A[j] = g_agg[etA][n*64 + j];
    B[j] = g_agg[etB][n*64 + j];
    X[j] = xin[n*64 + j];
    __syncthreads();
    const float* WlA = Wl + ia*4096; const float* WlB = Wl + ib*4096;
    const float* WrA = Wr + ia*4096; const float* WrB = Wr + ib*4096;
    float acc = __ldg(&bl[ia*64 + j]) + __ldg(&bl[ib*64 + j]);
    #pragma unroll 4
    for(int k=0;k<64;k++){
        acc = fmaf(A[k], __ldg(&WlA[j*64 + k]), acc);
        acc = fmaf(B[k], __ldg(&WlB[j*64 + k]), acc);
        acc = fmaf(X[k], __ldg(&WrA[j*64 + k]) + __ldg(&WrB[j*64 + k]), acc);
    }
    acc *= 0.5f;
    if(useRes) acc += X[j];
    out[n*64 + j] = fmaxf(acc, 0.0f);
}

// ---------------- edge head ----------------
__global__ void k_edge(const int* __restrict__ edges, const float* __restrict__ ea,
    const float* __restrict__ Wg1, const float* __restrict__ bg1,
    const float* __restrict__ Wg2, const float* __restrict__ bg2,
    const float* __restrict__ Wm1, const float* __restrict__ bm1,
    const float* __restrict__ Wm2, const float* __restrict__ bm2,
    const float* __restrict__ Wm3, const float* __restrict__ bm3,
    float* __restrict__ out){
    __shared__ float se[64], te[64], cat2[80], h1s[64], h2s[32], red[64];
    __shared__ float gsh;
    int e = blockIdx.x, j = threadIdx.x;
    int s = edges[4*EE + e];     // et=2 src
    int t = edges[5*EE + e];     // et=2 dst
    se[j] = g_sb[1][s*64 + j];
    te[j] = g_tb[1][t*64 + j];
    __syncthreads();
    float a = __ldg(&bg1[j]);
    #pragma unroll 4
    for(int k=0;k<64;k++) a = fmaf(se[k], __ldg(&Wg1[j*128 + k]), a);
    #pragma unroll 4
    for(int k=0;k<64;k++) a = fmaf(te[k], __ldg(&Wg1[j*128 + 64 + k]), a);
    a = fmaxf(a, 0.0f);
    red[j] = a * __ldg(&Wg2[j]);
    __syncthreads();
    if(j<32) red[j] += red[j+32]; __syncthreads();
    if(j<16) red[j] += red[j+16]; __syncthreads();
    if(j<8)  red[j] += red[j+8];  __syncthreads();
    if(j<4)  red[j] += red[j+4];  __syncthreads();
    if(j<2)  red[j] += red[j+2];  __syncthreads();
    if(j==0) gsh = sigf(red[0] + red[1] + __ldg(&bg2[0]));
    __syncthreads();
    float g = gsh;
    cat2[j] = g*se[j] + (1.0f - g)*te[j];
    if(j < 16) cat2[64 + j] = ea[e*16 + j];
    __syncthreads();
    float m = __ldg(&bm1[j]);
    #pragma unroll 4
    for(int k=0;k<80;k++) m = fmaf(cat2[k], __ldg(&Wm1[j*80 + k]), m);
    h1s[j] = fmaxf(m, 0.0f);
    __syncthreads();
    if(j < 32){
        float m2 = __ldg(&bm2[j]);
        #pragma unroll 4
        for(int k=0;k<64;k++) m2 = fmaf(h1s[k], __ldg(&Wm2[j*64 + k]), m2);
        h2s[j] = fmaxf(m2, 0.0f);
    }
    __syncthreads();
    if(j < 2){
        float o = __ldg(&bm3[j]);
        #pragma unroll
        for(int k=0;k<32;k++) o = fmaf(h2s[k], __ldg(&Wm3[j*32 + k]), o);
        out[e*2 + j] = o;
    }
}

// ---------------- host launcher ----------------
extern "C" void kernel_launch(void* const* d_in, const int* in_sizes, int n_in,
                              void* d_out, int out_size){
    const float* x_source = (const float*)d_in[0];
    const float* x_target = (const float*)d_in[1];
    const int*   edges    = (const int*)  d_in[2];
    const float* ea       = (const float*)d_in[3];
    const float* We_s1=(const float*)d_in[4];  const float* be_s1=(const float*)d_in[5];
    const float* We_s2=(const float*)d_in[6];  const float* be_s2=(const float*)d_in[7];
    const float* We_t1=(const float*)d_in[8];  const float* be_t1=(const float*)d_in[9];
    const float* We_t2=(const float*)d_in[10]; const float* be_t2=(const float*)d_in[11];
    const float* Wih=(const float*)d_in[12];   const float* Whh=(const float*)d_in[13];
    const float* bih=(const float*)d_in[14];   const float* bhh=(const float*)d_in[15];
    const float* Wl =(const float*)d_in[16];   const float* bl =(const float*)d_in[17];
    const float* Wr =(const float*)d_in[18];
    const float* Wg1=(const float*)d_in[19];   const float* bg1=(const float*)d_in[20];
    const float* Wg2=(const float*)d_in[21];   const float* bg2=(const float*)d_in[22];
    const float* Wm1=(const float*)d_in[23];   const float* bm1=(const float*)d_in[24];
    const float* Wm2=(const float*)d_in[25];   const float* bm2=(const float*)d_in[26];
    const float* Wm3=(const float*)d_in[27];   const float* bm3=(const float*)d_in[28];
    float* out = (float*)d_out;

    cudaFuncSetAttribute(k_lstm, cudaFuncAttributeMaxDynamicSharedMemorySize, 73728);

    k_zero    <<<(4*NN+255)/256, 256>>>();
    k_degree  <<<(4*EE+255)/256, 256>>>(edges);
    k_scan    <<<4, 1024>>>();
    k_scatter <<<(4*EE+255)/256, 256>>>(edges);
    k_buildnbr<<<(4*NN+127)/128, 128>>>();
    k_wperm   <<<(12*16384+255)/256, 256>>>(Whh);
    k_enc     <<<NN, 64>>>(x_source, 32, We_s1, be_s1, We_s2, be_s2, 0);
    k_enc     <<<NN, 64>>>(x_target, 24, We_t1, be_t1, We_t2, be_t2, 1);

    for(int L=0; L<3; L++){
        int in = L & 1, o = 1 - in;
        for(int et=0; et<4; et++){
            int i = L*4 + et;
            int srcIsT = (et==1 || et==3);
            k_U   <<<157, 256>>>(Wih, bih, bhh, i, srcIsT, in);
            k_lstm<<<313, 256, 73728>>>(i, et);
        }
        k_comb<<<NN, 64>>>(Wl, bl, Wr, L*4+0, L*4+3, 0, 3, in, o, 0, (L>0)?1:0);
        k_comb<<<NN, 64>>>(Wl, bl, Wr, L*4+1, L*4+2, 1, 2, in, o, 1, (L>0)?1:0);
    }
    k_edge<<<EE, 64>>>(edges, ea, Wg1, bg1, Wg2, bg2, Wm1, bm1, Wm2, bm2, Wm3, bm3, out);
}

// round 3
// speedup vs baseline: 1.1685x; 1.1678x over previous
#include <cuda_runtime.h>
#include <math.h>

#define NN 10000
#define HH 64
#define EE 40000
#define MD 12

typedef unsigned long long u64;
typedef unsigned int u32;

// ---------------- scratch (device globals; no allocation) ----------------
__device__ int   g_deg[4*NN];
__device__ int   g_start[4*NN];
__device__ int   g_cur[4*NN];
__device__ int   g_csr[4*EE];
__device__ int   g_nbr[4*NN*MD];
__device__ float g_sb[2][NN*HH];
__device__ float g_tb[2][NN*HH];
__device__ float g_agg[4][NN*HH];
__device__ float g_U[4][(NN+1)*256];
__device__ float g_Wp[12*64*256];   // permuted Whh: [blk][k][p]

// gate-permuted index: p -> row of Wih/Whh (torch gate order i,f,g,o)
// p = q*128 + lane*4 + gate, with d = 2*lane + q, row = gate*64 + d
__device__ __forceinline__ int pmap_row(int p){
    return (p & 3) * 64 + 2 * ((p >> 2) & 31) + (p >> 7);
}
// fast activations: MUFU only (EX2 + RCP), no IEEE div sequences
__device__ __forceinline__ float sigf(float x){
    return __fdividef(1.0f, 1.0f + __expf(-x));
}
__device__ __forceinline__ float tanhf_(float x){
    return fmaf(2.0f, __fdividef(1.0f, 1.0f + __expf(-2.0f*x)), -1.0f);
}

// ---------------- f32x2 packed helpers ----------------
__device__ __forceinline__ u64 pkf(float lo, float hi){
    u64 r; asm("mov.b64 %0, {%1,%2};" : "=l"(r) : "r"(__float_as_uint(lo)), "r"(__float_as_uint(hi))); return r;
}
__device__ __forceinline__ void upk(u64 v, float& lo, float& hi){
    u32 a, b;
    asm("mov.b64 {%0,%1}, %2;" : "=r"(a), "=r"(b) : "l"(v));
    lo = __uint_as_float(a); hi = __uint_as_float(b);
}
__device__ __forceinline__ u64 fma2_(u64 a, u64 b, u64 c){
    u64 d; asm("fma.rn.f32x2 %0, %1, %2, %3;" : "=l"(d) : "l"(a), "l"(b), "l"(c)); return d;
}

// ---------------- graph preprocessing ----------------
__global__ void k_zero(){
    int i = blockIdx.x*blockDim.x + threadIdx.x;
    if(i < 4*NN){ g_deg[i] = 0; g_cur[i] = 0; }
}

__global__ void k_degree(const int* __restrict__ edges){
    int i = blockIdx.x*blockDim.x + threadIdx.x;
    if(i >= 4*EE) return;
    int t = i / EE, e = i - t*EE;
    int dst = edges[t*2*EE + EE + e];
    atomicAdd(&g_deg[t*NN + dst], 1);
}

__global__ void k_scan(){
    __shared__ int sm[1024];
    int t = blockIdx.x, tid = threadIdx.x;
    const int CH = 10;
    int loc[CH]; int s = 0;
    int base = tid * CH;
    #pragma unroll
    for(int c=0;c<CH;c++){ int i = base + c; int v = (i<NN) ? g_deg[t*NN+i] : 0; loc[c] = v; s += v; }
    sm[tid] = s; __syncthreads();
    for(int off=1; off<1024; off<<=1){
        int v = (tid >= off) ? sm[tid-off] : 0;
        __syncthreads();
        sm[tid] += v;
        __syncthreads();
    }
    int run = sm[tid] - s;
    #pragma unroll
    for(int c=0;c<CH;c++){ int i = base + c; if(i < NN){ g_start[t*NN+i] = run; run += loc[c]; } }
}

__global__ void k_scatter(const int* __restrict__ edges){
    int i = blockIdx.x*blockDim.x + threadIdx.x;
    if(i >= 4*EE) return;
    int t = i / EE, e = i - t*EE;
    int src = edges[t*2*EE + e];
    int dst = edges[t*2*EE + EE + e];
    int p = atomicAdd(&g_cur[t*NN + dst], 1);
    g_csr[t*EE + g_start[t*NN + dst] + p] = src;
}

// top-12 smallest src per dst (incl. self loop), pad with sentinel NN
__global__ void k_buildnbr(){
    int i = blockIdx.x*blockDim.x + threadIdx.x;
    if(i >= 4*NN) return;
    int t = i / NN, n = i - t*NN;
    int arr[MD];
    #pragma unroll
    for(int k=0;k<MD;k++) arr[k] = 0x7fffffff;
    arr[0] = n;
    int st = g_start[t*NN + n], d = g_deg[t*NN + n];
    for(int q=0;q<d;q++){
        int v = g_csr[t*EE + st + q];
        if(v < arr[MD-1]){
            int j = MD-1;
            while(j > 0 && arr[j-1] > v){ arr[j] = arr[j-1]; j--; }
            arr[j] = v;
        }
    }
    int cnt = d + 1; if(cnt > MD) cnt = MD;
    #pragma unroll
    for(int k=0;k<MD;k++) g_nbr[i*MD + k] = (k < cnt) ? arr[k] : NN;
}

__global__ void k_wperm(const float* __restrict__ Whh){
    int idx = blockIdx.x*blockDim.x + threadIdx.x;
    if(idx >= 12*16384) return;
    int i = idx >> 14; int r = idx & 16383; int k = r >> 8; int p = r & 255;
    g_Wp[idx] = Whh[i*16384 + pmap_row(p)*64 + k];
}

// ---------------- node encoder (Linear-ReLU-Linear) ----------------
__global__ void k_enc(const float* __restrict__ x, int K,
                      const float* __restrict__ W1, const float* __restrict__ b1,
                      const float* __restrict__ W2, const float* __restrict__ b2,
                      int isT){
    __shared__ float xr[32];
    __shared__ float hid[64];
    int n = blockIdx.x, j = threadIdx.x;
    if(j < K) xr[j] = x[n*K + j];
    __syncthreads();
    float a = __ldg(&b1[j]);
    for(int k=0;k<K;k++) a = fmaf(xr[k], __ldg(&W1[j*K + k]), a);
    hid[j] = fmaxf(a, 0.0f);
    __syncthreads();
    float b = __ldg(&b2[j]);
    #pragma unroll 8
    for(int k=0;k<64;k++) b = fmaf(hid[k], __ldg(&W2[j*64 + k]), b);
    float* out = isT ? g_tb[0] : g_sb[0];
    out[n*64 + j] = b;
}

// ---- U = X @ Wih^T + bih + bhh (gate-permuted), row NN = bias only; grid.y = et ----
__global__ void k_U(const float* __restrict__ Wih, const float* __restrict__ bih,
                    const float* __restrict__ bhh, int L, int inSel){
    int et = blockIdx.y;
    int blk = L*4 + et;
    int isT = (et==1 || et==3);
    const float* x = isT ? g_tb[inSel] : g_sb[inSel];
    float* U = g_U[et];
    __shared__ float4 xsm[64*16];
    int p = threadIdx.x;
    int row = pmap_row(p);
    float bias = __ldg(&bih[blk*256 + row]) + __ldg(&bhh[blk*256 + row]);
    float4 w[16];
    const float4* wsrc = (const float4*)(Wih + (size_t)blk*16384 + row*64);
    #pragma unroll
    for(int q=0;q<16;q++) w[q] = __ldg(&wsrc[q]);
    int nb = blockIdx.x * 64;
    #pragma unroll
    for(int r=0;r<4;r++){
        int idx = p + r*256;
        int node = nb + (idx >> 4);
        float4 v = make_float4(0,0,0,0);
        if(node < NN) v = ((const float4*)x)[node*16 + (idx & 15)];
        xsm[idx] = v;
    }
    __syncthreads();
    for(int m=0;m<64;m++){
        int node = nb + m;
        if(node > NN) return;
        float acc = bias;
        #pragma unroll
        for(int q=0;q<16;q++){
            float4 xv = xsm[m*16 + q];
            acc = fmaf(xv.x, w[q].x, acc);
            acc = fmaf(xv.y, w[q].y, acc);
            acc = fmaf(xv.z, w[q].z, acc);
            acc = fmaf(xv.w, w[q].w, acc);
        }
        U[node*256 + p] = acc;
    }
}

// ---------------- LSTM aggregation (hot kernel) ----------------
// 1 warp = 8 nodes; permuted Whh in smem (64KB); h exchanged via smem; c in regs.
// Recurrent GEMM in packed fma.rn.f32x2; activations via MUFU EX2/RCP only.
__global__ void __launch_bounds__(256, 1) k_lstm(int L){
    extern __shared__ float smem[];
    float4* Wsm4 = (float4*)smem;            // 4096 float4 = 64KB
    float*  hsm  = smem + 16384;             // 64 nodes * 64 = 16KB
    int et = blockIdx.y;
    int blk = L*4 + et;
    int tid = threadIdx.x;
    const float4* wp = (const float4*)(g_Wp + (size_t)blk*16384);
    #pragma unroll
    for(int r=0;r<16;r++) Wsm4[tid + r*256] = wp[tid + r*256];
    #pragma unroll
    for(int r=0;r<16;r++) hsm[tid + r*256] = 0.0f;
    __syncthreads();

    int warp = tid>>5, lane = tid&31;
    int nbase = blockIdx.x*64 + warp*8;
    const int* nbr = g_nbr + et*NN*MD;
    const float4* U4 = (const float4*)g_U[et];
    float c0[8], c1[8];
    int nodes[8];
    #pragma unroll
    for(int m=0;m<8;m++){
        c0[m]=0.f; c1[m]=0.f;
        int n = nbase+m; nodes[m] = (n<NN)?n:(NN-1);
    }
    float* hbase = hsm + warp*8*64;

    for(int t=0;t<MD;t++){
        u64 if0[8], go0[8], if1[8], go1[8];
        #pragma unroll
        for(int m=0;m<8;m++){
            int nb = __ldg(&nbr[nodes[m]*MD + t]);
            float4 a0 = __ldg(&U4[nb*64 + lane]);
            float4 a1 = __ldg(&U4[nb*64 + 32 + lane]);
            if0[m] = pkf(a0.x, a0.y); go0[m] = pkf(a0.z, a0.w);
            if1[m] = pkf(a1.x, a1.y); go1[m] = pkf(a1.z, a1.w);
        }
        #pragma unroll
        for(int k0=0;k0<64;k0+=4){
            float4 h4[8];
            #pragma unroll
            for(int m=0;m<8;m++) h4[m] = *(const float4*)&hbase[m*64 + k0];
            #pragma unroll
            for(int dk=0;dk<4;dk++){
                const ulonglong2 wa = *(const ulonglong2*)&Wsm4[(k0+dk)*64 + lane];
                const ulonglong2 wb = *(const ulonglong2*)&Wsm4[(k0+dk)*64 + 32 + lane];
                #pragma unroll
                for(int m=0;m<8;m++){
                    float hv = (dk==0)?h4[m].x:(dk==1)?h4[m].y:(dk==2)?h4[m].z:h4[m].w;
                    u64 hv2 = pkf(hv, hv);
                    if0[m] = fma2_(hv2, wa.x, if0[m]);
                    go0[m] = fma2_(hv2, wa.y, go0[m]);
                    if1[m] = fma2_(hv2, wb.x, if1[m]);
                    go1[m] = fma2_(hv2, wb.y, go1[m]);
                }
            }
        }
        __syncwarp();
        #pragma unroll
        for(int m=0;m<8;m++){
            float pi0, pf0, pg0, po0, pi1, pf1, pg1, po1;
            upk(if0[m], pi0, pf0); upk(go0[m], pg0, po0);
            upk(if1[m], pi1, pf1); upk(go1[m], pg1, po1);
            float i0=sigf(pi0), f0=sigf(pf0), g0=tanhf_(pg0), o0=sigf(po0);
            float i1=sigf(pi1), f1=sigf(pf1), g1=tanhf_(pg1), o1=sigf(po1);
            c0[m] = fmaf(f0, c0[m], i0*g0);
            c1[m] = fmaf(f1, c1[m], i1*g1);
            float h0 = o0*tanhf_(c0[m]);
            float h1 = o1*tanhf_(c1[m]);
            *(float2*)&hbase[m*64 + 2*lane] = make_float2(h0, h1);
        }
        __syncwarp();
    }
    float* agg = g_agg[et];
    #pragma unroll
    for(int m=0;m<8;m++){
        int n = nbase + m;
        if(n < NN){
            float2 hv = *(const float2*)&hbase[m*64 + 2*lane];
            ((float2*)(agg + n*64))[lane] = hv;
        }
    }
}

// ---------------- per-layer combine: SAGE linear + hetero-mean + relu (+res) ----
__global__ void k_comb(const float* __restrict__ Wl, const float* __restrict__ bl,
                       const float* __restrict__ Wr,
                       int ia, int ib, int etA, int etB,
                       int inSel, int outSel, int isT, int useRes){
    __shared__ float A[64], B[64], X[64];
    int n = blockIdx.x, j = threadIdx.x;
    const float* xin = isT ? g_tb[inSel] : g_sb[inSel];
    float* out = isT ? g_tb[outSel] : g_sb[outSel];
    A[j] = g_agg[etA][n*64 + j];
    B[j] = g_agg[etB][n*64 + j];
    X[j] = xin[n*64 + j];
    __syncthreads();
    const float* WlA = Wl + ia*4096; const float* WlB = Wl + ib*4096;
    const float* WrA = Wr + ia*4096; const float* WrB = Wr + ib*4096;
    float acc = __ldg(&bl[ia*64 + j]) + __ldg(&bl[ib*64 + j]);
    #pragma unroll 4
    for(int k=0;k<64;k++){
        acc = fmaf(A[k], __ldg(&WlA[j*64 + k]), acc);
        acc = fmaf(B[k], __ldg(&WlB[j*64 + k]), acc);
        acc = fmaf(X[k], __ldg(&WrA[j*64 + k]) + __ldg(&WrB[j*64 + k]), acc);
    }
    acc *= 0.5f;
    if(useRes) acc += X[j];
    out[n*64 + j] = fmaxf(acc, 0.0f);
}

// ---------------- edge head ----------------
__global__ void k_edge(const int* __restrict__ edges, const float* __restrict__ ea,
    const float* __restrict__ Wg1, const float* __restrict__ bg1,
    const float* __restrict__ Wg2, const float* __restrict__ bg2,
    const float* __restrict__ Wm1, const float* __restrict__ bm1,
    const float* __restrict__ Wm2, const float* __restrict__ bm2,
    const float* __restrict__ Wm3, const float* __restrict__ bm3,
    float* __restrict__ out){
    __shared__ float se[64], te[64], cat2[80], h1s[64], h2s[32], red[64];
    __shared__ float gsh;
    int e = blockIdx.x, j = threadIdx.x;
    int s = edges[4*EE + e];
    int t = edges[5*EE + e];
    se[j] = g_sb[1][s*64 + j];
    te[j] = g_tb[1][t*64 + j];
    __syncthreads();
    float a = __ldg(&bg1[j]);
    #pragma unroll 4
    for(int k=0;k<64;k++) a = fmaf(se[k], __ldg(&Wg1[j*128 + k]), a);
    #pragma unroll 4
    for(int k=0;k<64;k++) a = fmaf(te[k], __ldg(&Wg1[j*128 + 64 + k]), a);
    a = fmaxf(a, 0.0f);
    red[j] = a * __ldg(&Wg2[j]);
    __syncthreads();
    if(j<32) red[j] += red[j+32]; __syncthreads();
    if(j<16) red[j] += red[j+16]; __syncthreads();
    if(j<8)  red[j] += red[j+8];  __syncthreads();
    if(j<4)  red[j] += red[j+4];  __syncthreads();
    if(j<2)  red[j] += red[j+2];  __syncthreads();
    if(j==0) gsh = sigf(red[0] + red[1] + __ldg(&bg2[0]));
    __syncthreads();
    float g = gsh;
    cat2[j] = g*se[j] + (1.0f - g)*te[j];
    if(j < 16) cat2[64 + j] = ea[e*16 + j];
    __syncthreads();
    float m = __ldg(&bm1[j]);
    #pragma unroll 4
    for(int k=0;k<80;k++) m = fmaf(cat2[k], __ldg(&Wm1[j*80 + k]), m);
    h1s[j] = fmaxf(m, 0.0f);
    __syncthreads();
    if(j < 32){
        float m2 = __ldg(&bm2[j]);
        #pragma unroll 4
        for(int k=0;k<64;k++) m2 = fmaf(h1s[k], __ldg(&Wm2[j*64 + k]), m2);
        h2s[j] = fmaxf(m2, 0.0f);
    }
    __syncthreads();
    if(j < 2){
        float o = __ldg(&bm3[j]);
        #pragma unroll
        for(int k=0;k<32;k++) o = fmaf(h2s[k], __ldg(&Wm3[j*32 + k]), o);
        out[e*2 + j] = o;
    }
}

// ---------------- host launcher ----------------
extern "C" void kernel_launch(void* const* d_in, const int* in_sizes, int n_in,
                              void* d_out, int out_size){
    const float* x_source = (const float*)d_in[0];
    const float* x_target = (const float*)d_in[1];
    const int*   edges    = (const int*)  d_in[2];
    const float* ea       = (const float*)d_in[3];
    const float* We_s1=(const float*)d_in[4];  const float* be_s1=(const float*)d_in[5];
    const float* We_s2=(const float*)d_in[6];  const float* be_s2=(const float*)d_in[7];
    const float* We_t1=(const float*)d_in[8];  const float* be_t1=(const float*)d_in[9];
    const float* We_t2=(const float*)d_in[10]; const float* be_t2=(const float*)d_in[11];
    const float* Wih=(const float*)d_in[12];   const float* Whh=(const float*)d_in[13];
    const float* bih=(const float*)d_in[14];   const float* bhh=(const float*)d_in[15];
    const float* Wl =(const float*)d_in[16];   const float* bl =(const float*)d_in[17];
    const float* Wr =(const float*)d_in[18];
    const float* Wg1=(const float*)d_in[19];   const float* bg1=(const float*)d_in[20];
    const float* Wg2=(const float*)d_in[21];   const float* bg2=(const float*)d_in[22];
    const float* Wm1=(const float*)d_in[23];   const float* bm1=(const float*)d_in[24];
    const float* Wm2=(const float*)d_in[25];   const float* bm2=(const float*)d_in[26];
    const float* Wm3=(const float*)d_in[27];   const float* bm3=(const float*)d_in[28];
    float* out = (float*)d_out;

    cudaFuncSetAttribute(k_lstm, cudaFuncAttributeMaxDynamicSharedMemorySize, 81920);

    k_zero    <<<(4*NN+255)/256, 256>>>();
    k_degree  <<<(4*EE+255)/256, 256>>>(edges);
    k_scan    <<<4, 1024>>>();
    k_scatter <<<(4*EE+255)/256, 256>>>(edges);
    k_buildnbr<<<(4*NN+127)/128, 128>>>();
    k_wperm   <<<(12*16384+255)/256, 256>>>(Whh);
    k_enc     <<<NN, 64>>>(x_source, 32, We_s1, be_s1, We_s2, be_s2, 0);
    k_enc     <<<NN, 64>>>(x_target, 24, We_t1, be_t1, We_t2, be_t2, 1);

    for(int L=0; L<3; L++){
        int in = L & 1, o = 1 - in;
        k_U   <<<dim3(157,4), 256>>>(Wih, bih, bhh, L, in);
        k_lstm<<<dim3(157,4), 256, 81920>>>(L);
        k_comb<<<NN, 64>>>(Wl, bl, Wr, L*4+0, L*4+3, 0, 3, in, o, 0, (L>0)?1:0);
        k_comb<<<NN, 64>>>(Wl, bl, Wr, L*4+1, L*4+2, 1, 2, in, o, 1, (L>0)?1:0);
    }
    k_edge<<<EE, 64>>>(edges, ea, Wg1, bg1, Wg2, bg2, Wm1, bm1, Wm2, bm2, Wm3, bm3, out);
}

// round 4
// speedup vs baseline: 4.5488x; 3.8928x over previous
#include <cuda_runtime.h>
#include <math.h>

#define NN 10000
#define HH 64
#define EE 40000
#define MD 12

typedef unsigned long long u64;
typedef unsigned int u32;

// ---------------- scratch (device globals; no allocation) ----------------
__device__ int   g_deg[4*NN];
__device__ int   g_start[4*NN];
__device__ int   g_cur[4*NN];
__device__ int   g_csr[4*EE];
__device__ int   g_nbr[4*NN*MD];
__device__ float g_sb[2][NN*HH];
__device__ float g_tb[2][NN*HH];
__device__ float g_agg[4][NN*HH];
__device__ float g_U[4][(NN+1)*256];
__device__ float g_Wp[12*64*256];     // permuted Whh: [blk][k][p]
__device__ float g_WihT[12*64*256];   // permuted Wih: [blk][k][p]
__device__ float g_bias2[12*256];     // bih+bhh, gate-permuted
// k-major transposed small weights
__device__ float g_WlT[12*64*64];
__device__ float g_WrT[12*64*64];
__device__ float g_Wg1T[128*64];
__device__ float g_Wm1T[80*64];
__device__ float g_Wm2T[64*32];
__device__ float g_Wm3T[32*2];
__device__ float g_E1sT[32*64];
__device__ float g_E2sT[64*64];
__device__ float g_E1tT[24*64];
__device__ float g_E2tT[64*64];

// gate-permuted index: p -> row of Wih/Whh (torch gate order i,f,g,o)
__device__ __forceinline__ int pmap_row(int p){
    return (p & 3) * 64 + 2 * ((p >> 2) & 31) + (p >> 7);
}
__device__ __forceinline__ float sigf(float x){
    return __fdividef(1.0f, 1.0f + __expf(-x));
}
__device__ __forceinline__ float tanhf_(float x){
    return fmaf(2.0f, __fdividef(1.0f, 1.0f + __expf(-2.0f*x)), -1.0f);
}

// ---------------- f32x2 packed helpers ----------------
__device__ __forceinline__ u64 pkf(float lo, float hi){
    u64 r; asm("mov.b64 %0, {%1,%2};" : "=l"(r) : "r"(__float_as_uint(lo)), "r"(__float_as_uint(hi))); return r;
}
__device__ __forceinline__ void upk(u64 v, float& lo, float& hi){
    u32 a, b;
    asm("mov.b64 {%0,%1}, %2;" : "=r"(a), "=r"(b) : "l"(v));
    lo = __uint_as_float(a); hi = __uint_as_float(b);
}
__device__ __forceinline__ u64 fma2_(u64 a, u64 b, u64 c){
    u64 d; asm("fma.rn.f32x2 %0, %1, %2, %3;" : "=l"(d) : "l"(a), "l"(b), "l"(c)); return d;
}

// ---------------- graph preprocessing ----------------
__global__ void k_zero(){
    int i = blockIdx.x*blockDim.x + threadIdx.x;
    if(i < 4*NN){ g_deg[i] = 0; g_cur[i] = 0; }
}

__global__ void k_degree(const int* __restrict__ edges){
    int i = blockIdx.x*blockDim.x + threadIdx.x;
    if(i >= 4*EE) return;
    int t = i / EE, e = i - t*EE;
    int dst = edges[t*2*EE + EE + e];
    atomicAdd(&g_deg[t*NN + dst], 1);
}

__global__ void k_scan(){
    __shared__ int sm[1024];
    int t = blockIdx.x, tid = threadIdx.x;
    const int CH = 10;
    int loc[CH]; int s = 0;
    int base = tid * CH;
    #pragma unroll
    for(int c=0;c<CH;c++){ int i = base + c; int v = (i<NN) ? g_deg[t*NN+i] : 0; loc[c] = v; s += v; }
    sm[tid] = s; __syncthreads();
    for(int off=1; off<1024; off<<=1){
        int v = (tid >= off) ? sm[tid-off] : 0;
        __syncthreads();
        sm[tid] += v;
        __syncthreads();
    }
    int run = sm[tid] - s;
    #pragma unroll
    for(int c=0;c<CH;c++){ int i = base + c; if(i < NN){ g_start[t*NN+i] = run; run += loc[c]; } }
}

__global__ void k_scatter(const int* __restrict__ edges){
    int i = blockIdx.x*blockDim.x + threadIdx.x;
    if(i >= 4*EE) return;
    int t = i / EE, e = i - t*EE;
    int src = edges[t*2*EE + e];
    int dst = edges[t*2*EE + EE + e];
    int p = atomicAdd(&g_cur[t*NN + dst], 1);
    g_csr[t*EE + g_start[t*NN + dst] + p] = src;
}

// top-12 smallest src per dst (incl. self loop), pad with sentinel NN
__global__ void k_buildnbr(){
    int i = blockIdx.x*blockDim.x + threadIdx.x;
    if(i >= 4*NN) return;
    int t = i / NN, n = i - t*NN;
    int arr[MD];
    #pragma unroll
    for(int k=0;k<MD;k++) arr[k] = 0x7fffffff;
    arr[0] = n;
    int st = g_start[t*NN + n], d = g_deg[t*NN + n];
    for(int q=0;q<d;q++){
        int v = g_csr[t*EE + st + q];
        if(v < arr[MD-1]){
            int j = MD-1;
            while(j > 0 && arr[j-1] > v){ arr[j] = arr[j-1]; j--; }
            arr[j] = v;
        }
    }
    int cnt = d + 1; if(cnt > MD) cnt = MD;
    #pragma unroll
    for(int k=0;k<MD;k++) g_nbr[i*MD + k] = (k < cnt) ? arr[k] : NN;
}

// Whh perm + Wih perm (k-major) + combined bias
__global__ void k_wperm(const float* __restrict__ Whh, const float* __restrict__ Wih,
                        const float* __restrict__ bih, const float* __restrict__ bhh){
    int idx = blockIdx.x*blockDim.x + threadIdx.x;
    if(idx < 12*16384){
        int i = idx >> 14; int r = idx & 16383; int k = r >> 8; int p = r & 255;
        g_Wp[idx] = Whh[i*16384 + pmap_row(p)*64 + k];
    } else if(idx < 2*12*16384){
        int j = idx - 12*16384;
        int i = j >> 14; int r = j & 16383; int k = r >> 8; int p = r & 255;
        g_WihT[j] = Wih[i*16384 + pmap_row(p)*64 + k];
    } else if(idx < 2*12*16384 + 12*256){
        int j = idx - 2*12*16384;
        int i = j >> 8; int p = j & 255; int row = pmap_row(p);
        g_bias2[j] = bih[i*256 + row] + bhh[i*256 + row];
    }
}

// transpose all small weights to k-major [k][j]
__global__ void k_prep(const float* __restrict__ Wl, const float* __restrict__ Wr,
                       const float* __restrict__ Wg1, const float* __restrict__ Wm1,
                       const float* __restrict__ Wm2, const float* __restrict__ Wm3,
                       const float* __restrict__ E1s, const float* __restrict__ E2s,
                       const float* __restrict__ E1t, const float* __restrict__ E2t){
    int idx = blockIdx.x*blockDim.x + threadIdx.x;
    if(idx < 49152){ int i=idx/4096, r=idx%4096, k=r/64, j=r%64; g_WlT[idx] = Wl[i*4096 + j*64 + k]; return; }
    idx -= 49152;
    if(idx < 49152){ int i=idx/4096, r=idx%4096, k=r/64, j=r%64; g_WrT[idx] = Wr[i*4096 + j*64 + k]; return; }
    idx -= 49152;
    if(idx < 8192){ int k=idx/64, j=idx%64; g_Wg1T[idx] = Wg1[j*128 + k]; return; }
    idx -= 8192;
    if(idx < 5120){ int k=idx/64, j=idx%64; g_Wm1T[idx] = Wm1[j*80 + k]; return; }
    idx -= 5120;
    if(idx < 2048){ int k=idx/32, j=idx%32; g_Wm2T[idx] = Wm2[j*64 + k]; return; }
    idx -= 2048;
    if(idx < 64){ int k=idx/2, j=idx%2; g_Wm3T[idx] = Wm3[j*32 + k]; return; }
    idx -= 64;
    if(idx < 2048){ int k=idx/64, j=idx%64; g_E1sT[idx] = E1s[j*32 + k]; return; }
    idx -= 2048;
    if(idx < 4096){ int k=idx/64, j=idx%64; g_E2sT[idx] = E2s[j*64 + k]; return; }
    idx -= 4096;
    if(idx < 1536){ int k=idx/64, j=idx%64; g_E1tT[idx] = E1t[j*24 + k]; return; }
    idx -= 1536;
    if(idx < 4096){ int k=idx/64, j=idx%64; g_E2tT[idx] = E2t[j*64 + k]; return; }
}

// ---------------- node encoder: 32 nodes/block, smem k-major weights ----
__global__ void k_enc(const float* __restrict__ x, int K,
                      const float* __restrict__ b1, const float* __restrict__ b2,
                      int isT){
    __shared__ float W1T[32*64];
    __shared__ float W2T[64*64];
    __shared__ float xin[32*32];
    __shared__ float hid[32*64];
    __shared__ float b1s[64], b2s[64];
    int tid = threadIdx.x;
    const float* w1src = isT ? g_E1tT : g_E1sT;
    const float* w2src = isT ? g_E2tT : g_E2sT;
    for(int i=tid;i<K*64;i+=256) W1T[i] = w1src[i];
    for(int i=tid;i<4096;i+=256) W2T[i] = w2src[i];
    if(tid < 64){ b1s[tid] = b1[tid]; b2s[tid] = b2[tid]; }
    int nb = blockIdx.x*32;
    for(int i=tid;i<32*K;i+=256){
        int node = nb + i/K;
        xin[i] = (node < NN) ? x[node*K + (i%K)] : 0.0f;
    }
    __syncthreads();
    int j = tid & 63, g = tid >> 6;
    #pragma unroll
    for(int mi=0;mi<8;mi++){
        int m = g*8 + mi;
        float a = b1s[j];
        for(int k=0;k<K;k++) a = fmaf(xin[m*K+k], W1T[k*64+j], a);
        hid[m*64+j] = fmaxf(a, 0.0f);
    }
    __syncthreads();
    float* out = isT ? g_tb[0] : g_sb[0];
    #pragma unroll
    for(int mi=0;mi<8;mi++){
        int m = g*8 + mi;
        int node = nb + m;
        float a = b2s[j];
        #pragma unroll 8
        for(int k=0;k<64;k++) a = fmaf(hid[m*64+k], W2T[k*64+j], a);
        if(node < NN) out[node*64+j] = a;
    }
}

// ---- U = X @ Wih^T + bias (gate-permuted); W column register-resident ----
__global__ void k_U(int L, int inSel){
    int et = blockIdx.y;
    int blk = L*4 + et;
    int isT = (et==1 || et==3);
    const float* x = isT ? g_tb[inSel] : g_sb[inSel];
    float* U = g_U[et];
    __shared__ float4 xsm[64*16];
    int p = threadIdx.x;
    float w[64];
    const float* wt = g_WihT + (size_t)blk*16384;
    #pragma unroll
    for(int k=0;k<64;k++) w[k] = wt[k*256 + p];
    float bias = g_bias2[blk*256 + p];
    int nb = blockIdx.x * 64;
    #pragma unroll
    for(int r=0;r<4;r++){
        int idx = p + r*256;
        int node = nb + (idx >> 4);
        float4 v = make_float4(0,0,0,0);
        if(node < NN) v = ((const float4*)x)[node*16 + (idx & 15)];
        xsm[idx] = v;
    }
    __syncthreads();
    for(int m=0;m<64;m++){
        int node = nb + m;
        if(node > NN) break;
        float acc = bias;
        #pragma unroll
        for(int q=0;q<16;q++){
            float4 xv = xsm[m*16 + q];
            acc = fmaf(xv.x, w[4*q+0], acc);
            acc = fmaf(xv.y, w[4*q+1], acc);
            acc = fmaf(xv.z, w[4*q+2], acc);
            acc = fmaf(xv.w, w[4*q+3], acc);
        }
        U[node*256 + p] = acc;
    }
}

// ---------------- LSTM aggregation (hot kernel) ----------------
__global__ void __launch_bounds__(256, 1) k_lstm(int L){
    extern __shared__ float smem[];
    float4* Wsm4 = (float4*)smem;
    float*  hsm  = smem + 16384;
    int et = blockIdx.y;
    int blk = L*4 + et;
    int tid = threadIdx.x;
    const float4* wp = (const float4*)(g_Wp + (size_t)blk*16384);
    #pragma unroll
    for(int r=0;r<16;r++) Wsm4[tid + r*256] = wp[tid + r*256];
    #pragma unroll
    for(int r=0;r<16;r++) hsm[tid + r*256] = 0.0f;
    __syncthreads();

    int warp = tid>>5, lane = tid&31;
    int nbase = blockIdx.x*64 + warp*8;
    const int* nbr = g_nbr + et*NN*MD;
    const float4* U4 = (const float4*)g_U[et];
    float c0[8], c1[8];
    int nodes[8];
    #pragma unroll
    for(int m=0;m<8;m++){
        c0[m]=0.f; c1[m]=0.f;
        int n = nbase+m; nodes[m] = (n<NN)?n:(NN-1);
    }
    float* hbase = hsm + warp*8*64;

    for(int t=0;t<MD;t++){
        u64 if0[8], go0[8], if1[8], go1[8];
        #pragma unroll
        for(int m=0;m<8;m++){
            int nb = __ldg(&nbr[nodes[m]*MD + t]);
            float4 a0 = __ldg(&U4[nb*64 + lane]);
            float4 a1 = __ldg(&U4[nb*64 + 32 + lane]);
            if0[m] = pkf(a0.x, a0.y); go0[m] = pkf(a0.z, a0.w);
            if1[m] = pkf(a1.x, a1.y); go1[m] = pkf(a1.z, a1.w);
        }
        #pragma unroll
        for(int k0=0;k0<64;k0+=4){
            float4 h4[8];
            #pragma unroll
            for(int m=0;m<8;m++) h4[m] = *(const float4*)&hbase[m*64 + k0];
            #pragma unroll
            for(int dk=0;dk<4;dk++){
                const ulonglong2 wa = *(const ulonglong2*)&Wsm4[(k0+dk)*64 + lane];
                const ulonglong2 wb = *(const ulonglong2*)&Wsm4[(k0+dk)*64 + 32 + lane];
                #pragma unroll
                for(int m=0;m<8;m++){
                    float hv = (dk==0)?h4[m].x:(dk==1)?h4[m].y:(dk==2)?h4[m].z:h4[m].w;
                    u64 hv2 = pkf(hv, hv);
                    if0[m] = fma2_(hv2, wa.x, if0[m]);
                    go0[m] = fma2_(hv2, wa.y, go0[m]);
                    if1[m] = fma2_(hv2, wb.x, if1[m]);
                    go1[m] = fma2_(hv2, wb.y, go1[m]);
                }
            }
        }
        __syncwarp();
        #pragma unroll
        for(int m=0;m<8;m++){
            float pi0, pf0, pg0, po0, pi1, pf1, pg1, po1;
            upk(if0[m], pi0, pf0); upk(go0[m], pg0, po0);
            upk(if1[m], pi1, pf1); upk(go1[m], pg1, po1);
            float i0=sigf(pi0), f0=sigf(pf0), g0=tanhf_(pg0), o0=sigf(po0);
            float i1=sigf(pi1), f1=sigf(pf1), g1=tanhf_(pg1), o1=sigf(po1);
            c0[m] = fmaf(f0, c0[m], i0*g0);
            c1[m] = fmaf(f1, c1[m], i1*g1);
            float h0 = o0*tanhf_(c0[m]);
            float h1 = o1*tanhf_(c1[m]);
            *(float2*)&hbase[m*64 + 2*lane] = make_float2(h0, h1);
        }
        __syncwarp();
    }
    float* agg = g_agg[et];
    #pragma unroll
    for(int m=0;m<8;m++){
        int n = nbase + m;
        if(n < NN){
            float2 hv = *(const float2*)&hbase[m*64 + 2*lane];
            ((float2*)(agg + n*64))[lane] = hv;
        }
    }
}

// ---- combine: 32 nodes/block, smem k-major weights ----
__global__ void k_comb(const float* __restrict__ bl,
                       int ia, int ib, int etA, int etB,
                       int inSel, int outSel, int isT, int useRes){
    extern __shared__ float cs[];
    float* WlAT = cs;
    float* WlBT = cs + 4096;
    float* WrST = cs + 8192;
    float* A    = cs + 12288;
    float* B    = cs + 14336;
    float* X    = cs + 16384;
    float* blj  = cs + 18432;
    int tid = threadIdx.x;
    const float* wa = g_WlT + ia*4096;
    const float* wb = g_WlT + ib*4096;
    const float* ra = g_WrT + ia*4096;
    const float* rb = g_WrT + ib*4096;
    for(int i=tid;i<4096;i+=256){
        WlAT[i] = wa[i];
        WlBT[i] = wb[i];
        WrST[i] = ra[i] + rb[i];
    }
    if(tid < 64) blj[tid] = bl[ia*64+tid] + bl[ib*64+tid];
    int nb = blockIdx.x*32;
    const float* xin = isT ? g_tb[inSel] : g_sb[inSel];
    for(int i=tid;i<2048;i+=256){
        int node = nb + (i>>6); int c = i & 63;
        bool ok = node < NN;
        A[i] = ok ? g_agg[etA][node*64+c] : 0.0f;
        B[i] = ok ? g_agg[etB][node*64+c] : 0.0f;
        X[i] = ok ? xin[node*64+c] : 0.0f;
    }
    __syncthreads();
    int j = tid & 63, g = tid >> 6;
    float* out = isT ? g_tb[outSel] : g_sb[outSel];
    #pragma unroll
    for(int mi=0;mi<8;mi++){
        int m = g*8 + mi;
        int node = nb + m;
        float acc = blj[j];
        #pragma unroll 4
        for(int k=0;k<64;k++){
            acc = fmaf(A[m*64+k], WlAT[k*64+j], acc);
            acc = fmaf(B[m*64+k], WlBT[k*64+j], acc);
            acc = fmaf(X[m*64+k], WrST[k*64+j], acc);
        }
        acc *= 0.5f;
        if(useRes) acc += X[m*64+j];
        if(node < NN) out[node*64+j] = fmaxf(acc, 0.0f);
    }
}

// ---- edge head: 32 edges/block, smem k-major weights ----
__global__ void k_edge(const int* __restrict__ edges, const float* __restrict__ ea,
    const float* __restrict__ bg1, const float* __restrict__ Wg2, const float* __restrict__ bg2,
    const float* __restrict__ bm1, const float* __restrict__ bm2, const float* __restrict__ bm3,
    float* __restrict__ out){
    extern __shared__ float es[];
    float* Wg1T = es;               // 8192
    float* Wm1T = es + 8192;        // 5120
    float* Wm2T = es + 13312;       // 2048
    float* Wm3T = es + 15360;       // 64
    float* cvec = es + 15424;       // 256
    float* se   = es + 15680;       // 2048
    float* te   = es + 17728;       // 2048
    float* cat  = es + 19776;       // 2560
    float* h1   = es + 22336;       // 2048
    float* h2   = es + 24384;       // 1024
    float* red  = es + 25408;       // 64
    __shared__ int sidx[32], tidx[32];
    int tid = threadIdx.x;
    for(int i=tid;i<8192;i+=256) Wg1T[i] = g_Wg1T[i];
    for(int i=tid;i<5120;i+=256) Wm1T[i] = g_Wm1T[i];
    for(int i=tid;i<2048;i+=256) Wm2T[i] = g_Wm2T[i];
    if(tid < 64)  Wm3T[tid] = g_Wm3T[tid];
    if(tid < 64)  cvec[tid] = bg1[tid];
    else if(tid < 128) cvec[tid] = Wg2[tid-64];
    else if(tid < 192) cvec[tid] = bm1[tid-128];
    else if(tid < 224) cvec[tid] = bm2[tid-192];
    else if(tid == 224) cvec[224] = bm3[0];
    else if(tid == 225) cvec[225] = bm3[1];
    else if(tid == 226) cvec[226] = bg2[0];
    int ebase = blockIdx.x*32;
    if(tid < 32){
        sidx[tid] = edges[4*EE + ebase + tid];
        tidx[tid] = edges[5*EE + ebase + tid];
    }
    __syncthreads();
    for(int i=tid;i<2048;i+=256){
        int e = i >> 6, c = i & 63;
        se[i] = g_sb[1][sidx[e]*64 + c];
        te[i] = g_tb[1][tidx[e]*64 + c];
    }
    __syncthreads();
    int j = tid & 63, g = tid >> 6;
    int half = (tid >> 5) & 1;
    // Phase A: gate hidden dot Wg2, warp-reduced
    #pragma unroll
    for(int ei=0;ei<8;ei++){
        int e = g*8 + ei;
        float a = cvec[j];
        #pragma unroll 4
        for(int k=0;k<64;k++) a = fmaf(se[e*64+k], Wg1T[k*64+j], a);
        #pragma unroll 4
        for(int k=0;k<64;k++) a = fmaf(te[e*64+k], Wg1T[(64+k)*64+j], a);
        a = fmaxf(a, 0.0f);
        float v = a * cvec[64+j];
        #pragma unroll
        for(int off=16;off>0;off>>=1) v += __shfl_xor_sync(0xffffffffu, v, off);
        if((tid & 31) == 0) red[e*2 + half] = v;
    }
    __syncthreads();
    // Phase B: gate value, er || ea
    #pragma unroll
    for(int ei=0;ei<8;ei++){
        int e = g*8 + ei;
        float gv = sigf(red[e*2] + red[e*2+1] + cvec[226]);
        cat[e*80 + j] = gv*se[e*64+j] + (1.0f-gv)*te[e*64+j];
        if(j < 16) cat[e*80 + 64 + j] = ea[(ebase+e)*16 + j];
    }
    __syncthreads();
    // Phase C: m1
    #pragma unroll
    for(int ei=0;ei<8;ei++){
        int e = g*8 + ei;
        float m = cvec[128+j];
        #pragma unroll 4
        for(int k=0;k<80;k++) m = fmaf(cat[e*80+k], Wm1T[k*64+j], m);
        h1[e*64+j] = fmaxf(m, 0.0f);
    }
    __syncthreads();
    // Phase D: m2 (j<32)
    if(j < 32){
        #pragma unroll
        for(int ei=0;ei<8;ei++){
            int e = g*8 + ei;
            float m = cvec[192+j];
            #pragma unroll 4
            for(int k=0;k<64;k++) m = fmaf(h1[e*64+k], Wm2T[k*32+j], m);
            h2[e*32+j] = fmaxf(m, 0.0f);
        }
    }
    __syncthreads();
    // Phase E: m3 (j<2)
    if(j < 2){
        #pragma unroll
        for(int ei=0;ei<8;ei++){
            int e = g*8 + ei;
            float o = cvec[224+j];
            #pragma unroll
            for(int k=0;k<32;k++) o = fmaf(h2[e*32+k], Wm3T[k*2+j], o);
            out[(ebase+e)*2 + j] = o;
        }
    }
}

// ---------------- host launcher ----------------
extern "C" void kernel_launch(void* const* d_in, const int* in_sizes, int n_in,
                              void* d_out, int out_size){
    const float* x_source = (const float*)d_in[0];
    const float* x_target = (const float*)d_in[1];
    const int*   edges    = (const int*)  d_in[2];
    const float* ea       = (const float*)d_in[3];
    const float* We_s1=(const float*)d_in[4];  const float* be_s1=(const float*)d_in[5];
    const float* We_s2=(const float*)d_in[6];  const float* be_s2=(const float*)d_in[7];
    const float* We_t1=(const float*)d_in[8];  const float* be_t1=(const float*)d_in[9];
    const float* We_t2=(const float*)d_in[10]; const float* be_t2=(const float*)d_in[11];
    const float* Wih=(const float*)d_in[12];   const float* Whh=(const float*)d_in[13];
    const float* bih=(const float*)d_in[14];   const float* bhh=(const float*)d_in[15];
    const float* Wl =(const float*)d_in[16];   const float* bl =(const float*)d_in[17];
    const float* Wr =(const float*)d_in[18];
    const float* Wg1=(const float*)d_in[19];   const float* bg1=(const float*)d_in[20];
    const float* Wg2=(const float*)d_in[21];   const float* bg2=(const float*)d_in[22];
    const float* Wm1=(const float*)d_in[23];   const float* bm1=(const float*)d_in[24];
    const float* Wm2=(const float*)d_in[25];   const float* bm2=(const float*)d_in[26];
    const float* Wm3=(const float*)d_in[27];   const float* bm3=(const float*)d_in[28];
    float* out = (float*)d_out;

    cudaFuncSetAttribute(k_lstm, cudaFuncAttributeMaxDynamicSharedMemorySize, 81920);
    cudaFuncSetAttribute(k_comb, cudaFuncAttributeMaxDynamicSharedMemorySize, 75776);
    cudaFuncSetAttribute(k_edge, cudaFuncAttributeMaxDynamicSharedMemorySize, 102400);

    k_zero    <<<(4*NN+255)/256, 256>>>();
    k_degree  <<<(4*EE+255)/256, 256>>>(edges);
    k_scan    <<<4, 1024>>>();
    k_scatter <<<(4*EE+255)/256, 256>>>(edges);
    k_buildnbr<<<(4*NN+127)/128, 128>>>();
    k_wperm   <<<(2*12*16384 + 12*256 + 255)/256, 256>>>(Whh, Wih, bih, bhh);
    k_prep    <<<(125504+255)/256, 256>>>(Wl, Wr, Wg1, Wm1, Wm2, Wm3, We_s1, We_s2, We_t1, We_t2);
    k_enc     <<<313, 256>>>(x_source, 32, be_s1, be_s2, 0);
    k_enc     <<<313, 256>>>(x_target, 24, be_t1, be_t2, 1);

    for(int L=0; L<3; L++){
        int in = L & 1, o = 1 - in;
        k_U   <<<dim3(157,4), 256>>>(L, in);
        k_lstm<<<dim3(157,4), 256, 81920>>>(L);
        k_comb<<<313, 256, 75776>>>(bl, L*4+0, L*4+3, 0, 3, in, o, 0, (L>0)?1:0);
        k_comb<<<313, 256, 75776>>>(bl, L*4+1, L*4+2, 1, 2, in, o, 1, (L>0)?1:0);
    }
    k_edge<<<1250, 256, 102400>>>(edges, ea, bg1, Wg2, bg2, bm1, bm2, bm3, out);
}

// round 5
// speedup vs baseline: 4.6799x; 1.0288x over previous
#include <cuda_runtime.h>
#include <math.h>

#define NN 10000
#define HH 64
#define EE 40000
#define MD 12

typedef unsigned long long u64;
typedef unsigned int u32;

// ---------------- scratch (device globals; no allocation) ----------------
__device__ int   g_deg[4*NN];
__device__ int   g_start[4*NN];
__device__ int   g_cur[4*NN];
__device__ int   g_csr[4*EE];
__device__ int   g_nbr[4*NN*MD];
__device__ float g_sb[2][NN*HH];
__device__ float g_tb[2][NN*HH];
__device__ float g_agg[4][NN*HH];
__device__ float g_U[4][(NN+1)*256];
__device__ float g_Wp[12*64*256];     // permuted Whh: [blk][k][p]
__device__ float g_WihT[12*64*256];   // permuted Wih: [blk][k][p]
__device__ float g_bias2[12*256];     // bih+bhh, gate-permuted
// k-major transposed small weights
__device__ float g_WlT[12*64*64];
__device__ float g_WrT[12*64*64];
__device__ float g_Wg1T[128*64];
__device__ float g_Wm1T[80*64];
__device__ float g_Wm2T[64*32];
__device__ float g_Wm3T[32*2];
__device__ float g_E1sT[32*64];
__device__ float g_E2sT[64*64];
__device__ float g_E1tT[24*64];
__device__ float g_E2tT[64*64];

// gate-permuted index: p -> row of Wih/Whh (torch gate order i,f,g,o)
__device__ __forceinline__ int pmap_row(int p){
    return (p & 3) * 64 + 2 * ((p >> 2) & 31) + (p >> 7);
}
__device__ __forceinline__ float sigf(float x){
    return __fdividef(1.0f, 1.0f + __expf(-x));
}
__device__ __forceinline__ float tanhf_(float x){
    return fmaf(2.0f, __fdividef(1.0f, 1.0f + __expf(-2.0f*x)), -1.0f);
}

// ---------------- f32x2 packed helpers ----------------
__device__ __forceinline__ u64 pkf(float lo, float hi){
    u64 r; asm("mov.b64 %0, {%1,%2};" : "=l"(r) : "r"(__float_as_uint(lo)), "r"(__float_as_uint(hi))); return r;
}
__device__ __forceinline__ void upk(u64 v, float& lo, float& hi){
    u32 a, b;
    asm("mov.b64 {%0,%1}, %2;" : "=r"(a), "=r"(b) : "l"(v));
    lo = __uint_as_float(a); hi = __uint_as_float(b);
}
__device__ __forceinline__ u64 fma2_(u64 a, u64 b, u64 c){
    u64 d; asm("fma.rn.f32x2 %0, %1, %2, %3;" : "=l"(d) : "l"(a), "l"(b), "l"(c)); return d;
}

// ---------------- graph preprocessing ----------------
__global__ void k_zero(){
    int i = blockIdx.x*blockDim.x + threadIdx.x;
    if(i < 4*NN){ g_deg[i] = 0; g_cur[i] = 0; }
}

__global__ void k_degree(const int* __restrict__ edges){
    int i = blockIdx.x*blockDim.x + threadIdx.x;
    if(i >= 4*EE) return;
    int t = i / EE, e = i - t*EE;
    int dst = edges[t*2*EE + EE + e];
    atomicAdd(&g_deg[t*NN + dst], 1);
}

__global__ void k_scan(){
    __shared__ int sm[1024];
    int t = blockIdx.x, tid = threadIdx.x;
    const int CH = 10;
    int loc[CH]; int s = 0;
    int base = tid * CH;
    #pragma unroll
    for(int c=0;c<CH;c++){ int i = base + c; int v = (i<NN) ? g_deg[t*NN+i] : 0; loc[c] = v; s += v; }
    sm[tid] = s; __syncthreads();
    for(int off=1; off<1024; off<<=1){
        int v = (tid >= off) ? sm[tid-off] : 0;
        __syncthreads();
        sm[tid] += v;
        __syncthreads();
    }
    int run = sm[tid] - s;
    #pragma unroll
    for(int c=0;c<CH;c++){ int i = base + c; if(i < NN){ g_start[t*NN+i] = run; run += loc[c]; } }
}

__global__ void k_scatter(const int* __restrict__ edges){
    int i = blockIdx.x*blockDim.x + threadIdx.x;
    if(i >= 4*EE) return;
    int t = i / EE, e = i - t*EE;
    int src = edges[t*2*EE + e];
    int dst = edges[t*2*EE + EE + e];
    int p = atomicAdd(&g_cur[t*NN + dst], 1);
    g_csr[t*EE + g_start[t*NN + dst] + p] = src;
}

// top-12 smallest src per dst (incl. self loop), pad with sentinel NN
__global__ void k_buildnbr(){
    int i = blockIdx.x*blockDim.x + threadIdx.x;
    if(i >= 4*NN) return;
    int t = i / NN, n = i - t*NN;
    int arr[MD];
    #pragma unroll
    for(int k=0;k<MD;k++) arr[k] = 0x7fffffff;
    arr[0] = n;
    int st = g_start[t*NN + n], d = g_deg[t*NN + n];
    for(int q=0;q<d;q++){
        int v = g_csr[t*EE + st + q];
        if(v < arr[MD-1]){
            int j = MD-1;
            while(j > 0 && arr[j-1] > v){ arr[j] = arr[j-1]; j--; }
            arr[j] = v;
        }
    }
    int cnt = d + 1; if(cnt > MD) cnt = MD;
    #pragma unroll
    for(int k=0;k<MD;k++) g_nbr[i*MD + k] = (k < cnt) ? arr[k] : NN;
}

// Whh perm + Wih perm (k-major) + combined bias
__global__ void k_wperm(const float* __restrict__ Whh, const float* __restrict__ Wih,
                        const float* __restrict__ bih, const float* __restrict__ bhh){
    int idx = blockIdx.x*blockDim.x + threadIdx.x;
    if(idx < 12*16384){
        int i = idx >> 14; int r = idx & 16383; int k = r >> 8; int p = r & 255;
        g_Wp[idx] = Whh[i*16384 + pmap_row(p)*64 + k];
    } else if(idx < 2*12*16384){
        int j = idx - 12*16384;
        int i = j >> 14; int r = j & 16383; int k = r >> 8; int p = r & 255;
        g_WihT[j] = Wih[i*16384 + pmap_row(p)*64 + k];
    } else if(idx < 2*12*16384 + 12*256){
        int j = idx - 2*12*16384;
        int i = j >> 8; int p = j & 255; int row = pmap_row(p);
        g_bias2[j] = bih[i*256 + row] + bhh[i*256 + row];
    }
}

// transpose all small weights to k-major [k][j]
__global__ void k_prep(const float* __restrict__ Wl, const float* __restrict__ Wr,
                       const float* __restrict__ Wg1, const float* __restrict__ Wm1,
                       const float* __restrict__ Wm2, const float* __restrict__ Wm3,
                       const float* __restrict__ E1s, const float* __restrict__ E2s,
                       const float* __restrict__ E1t, const float* __restrict__ E2t){
    int idx = blockIdx.x*blockDim.x + threadIdx.x;
    if(idx < 49152){ int i=idx/4096, r=idx%4096, k=r/64, j=r%64; g_WlT[idx] = Wl[i*4096 + j*64 + k]; return; }
    idx -= 49152;
    if(idx < 49152){ int i=idx/4096, r=idx%4096, k=r/64, j=r%64; g_WrT[idx] = Wr[i*4096 + j*64 + k]; return; }
    idx -= 49152;
    if(idx < 8192){ int k=idx/64, j=idx%64; g_Wg1T[idx] = Wg1[j*128 + k]; return; }
    idx -= 8192;
    if(idx < 5120){ int k=idx/64, j=idx%64; g_Wm1T[idx] = Wm1[j*80 + k]; return; }
    idx -= 5120;
    if(idx < 2048){ int k=idx/32, j=idx%32; g_Wm2T[idx] = Wm2[j*64 + k]; return; }
    idx -= 2048;
    if(idx < 64){ int k=idx/2, j=idx%2; g_Wm3T[idx] = Wm3[j*32 + k]; return; }
    idx -= 64;
    if(idx < 2048){ int k=idx/64, j=idx%64; g_E1sT[idx] = E1s[j*32 + k]; return; }
    idx -= 2048;
    if(idx < 4096){ int k=idx/64, j=idx%64; g_E2sT[idx] = E2s[j*64 + k]; return; }
    idx -= 4096;
    if(idx < 1536){ int k=idx/64, j=idx%64; g_E1tT[idx] = E1t[j*24 + k]; return; }
    idx -= 1536;
    if(idx < 4096){ int k=idx/64, j=idx%64; g_E2tT[idx] = E2t[j*64 + k]; return; }
}

// ---------------- node encoder: 32 nodes/block, smem k-major weights ----
__global__ void k_enc(const float* __restrict__ x, int K,
                      const float* __restrict__ b1, const float* __restrict__ b2,
                      int isT){
    __shared__ float W1T[32*64];
    __shared__ float W2T[64*64];
    __shared__ float xin[32*32];
    __shared__ float hid[32*64];
    __shared__ float b1s[64], b2s[64];
    int tid = threadIdx.x;
    const float* w1src = isT ? g_E1tT : g_E1sT;
    const float* w2src = isT ? g_E2tT : g_E2sT;
    for(int i=tid;i<K*64;i+=256) W1T[i] = w1src[i];
    for(int i=tid;i<4096;i+=256) W2T[i] = w2src[i];
    if(tid < 64){ b1s[tid] = b1[tid]; b2s[tid] = b2[tid]; }
    int nb = blockIdx.x*32;
    for(int i=tid;i<32*K;i+=256){
        int node = nb + i/K;
        xin[i] = (node < NN) ? x[node*K + (i%K)] : 0.0f;
    }
    __syncthreads();
    int j = tid & 63, g = tid >> 6;
    #pragma unroll
    for(int mi=0;mi<8;mi++){
        int m = g*8 + mi;
        float a = b1s[j];
        for(int k=0;k<K;k++) a = fmaf(xin[m*K+k], W1T[k*64+j], a);
        hid[m*64+j] = fmaxf(a, 0.0f);
    }
    __syncthreads();
    float* out = isT ? g_tb[0] : g_sb[0];
    #pragma unroll
    for(int mi=0;mi<8;mi++){
        int m = g*8 + mi;
        int node = nb + m;
        float a = b2s[j];
        #pragma unroll 8
        for(int k=0;k<64;k++) a = fmaf(hid[m*64+k], W2T[k*64+j], a);
        if(node < NN) out[node*64+j] = a;
    }
}

// ---- U = X @ Wih^T + bias (gate-permuted); W column register-resident ----
__global__ void k_U(int L, int inSel){
    int et = blockIdx.y;
    int blk = L*4 + et;
    int isT = (et==1 || et==3);
    const float* x = isT ? g_tb[inSel] : g_sb[inSel];
    float* U = g_U[et];
    __shared__ float4 xsm[64*16];
    int p = threadIdx.x;
    float w[64];
    const float* wt = g_WihT + (size_t)blk*16384;
    #pragma unroll
    for(int k=0;k<64;k++) w[k] = wt[k*256 + p];
    float bias = g_bias2[blk*256 + p];
    int nb = blockIdx.x * 64;
    #pragma unroll
    for(int r=0;r<4;r++){
        int idx = p + r*256;
        int node = nb + (idx >> 4);
        float4 v = make_float4(0,0,0,0);
        if(node < NN) v = ((const float4*)x)[node*16 + (idx & 15)];
        xsm[idx] = v;
    }
    __syncthreads();
    for(int m=0;m<64;m++){
        int node = nb + m;
        if(node > NN) break;
        float acc = bias;
        #pragma unroll
        for(int q=0;q<16;q++){
            float4 xv = xsm[m*16 + q];
            acc = fmaf(xv.x, w[4*q+0], acc);
            acc = fmaf(xv.y, w[4*q+1], acc);
            acc = fmaf(xv.z, w[4*q+2], acc);
            acc = fmaf(xv.w, w[4*q+3], acc);
        }
        U[node*256 + p] = acc;
    }
}

// ---------------- LSTM aggregation (hot kernel) ----------------
// 2 CTAs/SM (4 warps/SMSP) to hide LDS/LDG/MUFU latency behind FMA issue.
__global__ void __launch_bounds__(256, 2) k_lstm(int L){
    extern __shared__ float smem[];
    float4* Wsm4 = (float4*)smem;            // 64KB
    float*  hsm  = smem + 16384;             // 16KB
    int et = blockIdx.y;
    int blk = L*4 + et;
    int tid = threadIdx.x;
    const float4* wp = (const float4*)(g_Wp + (size_t)blk*16384);
    #pragma unroll
    for(int r=0;r<16;r++) Wsm4[tid + r*256] = wp[tid + r*256];
    #pragma unroll
    for(int r=0;r<16;r++) hsm[tid + r*256] = 0.0f;
    __syncthreads();

    int warp = tid>>5, lane = tid&31;
    int nbase = blockIdx.x*64 + warp*8;
    const int* nbr = g_nbr + et*NN*MD;
    const float4* U4 = (const float4*)g_U[et];
    float c0[8], c1[8];
    int nodes[8];
    #pragma unroll
    for(int m=0;m<8;m++){
        c0[m]=0.f; c1[m]=0.f;
        int n = nbase+m; nodes[m] = (n<NN)?n:(NN-1);
    }
    float* hbase = hsm + warp*8*64;

    for(int t=0;t<MD;t++){
        u64 if0[8], go0[8], if1[8], go1[8];
        #pragma unroll
        for(int m=0;m<8;m++){
            int nb = __ldg(&nbr[nodes[m]*MD + t]);
            float4 a0 = __ldg(&U4[nb*64 + lane]);
            float4 a1 = __ldg(&U4[nb*64 + 32 + lane]);
            if0[m] = pkf(a0.x, a0.y); go0[m] = pkf(a0.z, a0.w);
            if1[m] = pkf(a1.x, a1.y); go1[m] = pkf(a1.z, a1.w);
        }
        #pragma unroll
        for(int k0=0;k0<64;k0+=4){
            float4 h4[8];
            #pragma unroll
            for(int m=0;m<8;m++) h4[m] = *(const float4*)&hbase[m*64 + k0];
            #pragma unroll
            for(int dk=0;dk<4;dk++){
                const ulonglong2 wa = *(const ulonglong2*)&Wsm4[(k0+dk)*64 + lane];
                const ulonglong2 wb = *(const ulonglong2*)&Wsm4[(k0+dk)*64 + 32 + lane];
                #pragma unroll
                for(int m=0;m<8;m++){
                    float hv = (dk==0)?h4[m].x:(dk==1)?h4[m].y:(dk==2)?h4[m].z:h4[m].w;
                    u64 hv2 = pkf(hv, hv);
                    if0[m] = fma2_(hv2, wa.x, if0[m]);
                    go0[m] = fma2_(hv2, wa.y, go0[m]);
                    if1[m] = fma2_(hv2, wb.x, if1[m]);
                    go1[m] = fma2_(hv2, wb.y, go1[m]);
                }
            }
        }
        __syncwarp();
        #pragma unroll
        for(int m=0;m<8;m++){
            float pi0, pf0, pg0, po0, pi1, pf1, pg1, po1;
            upk(if0[m], pi0, pf0); upk(go0[m], pg0, po0);
            upk(if1[m], pi1, pf1); upk(go1[m], pg1, po1);
            float i0=sigf(pi0), f0=sigf(pf0), g0=tanhf_(pg0), o0=sigf(po0);
            float i1=sigf(pi1), f1=sigf(pf1), g1=tanhf_(pg1), o1=sigf(po1);
            c0[m] = fmaf(f0, c0[m], i0*g0);
            c1[m] = fmaf(f1, c1[m], i1*g1);
            float h0 = o0*tanhf_(c0[m]);
            float h1 = o1*tanhf_(c1[m]);
            *(float2*)&hbase[m*64 + 2*lane] = make_float2(h0, h1);
        }
        __syncwarp();
    }
    float* agg = g_agg[et];
    #pragma unroll
    for(int m=0;m<8;m++){
        int n = nbase + m;
        if(n < NN){
            float2 hv = *(const float2*)&hbase[m*64 + 2*lane];
            ((float2*)(agg + n*64))[lane] = hv;
        }
    }
}

// ---- combine: 32 nodes/block, smem k-major weights; grid.y selects variant ----
__global__ void k_comb(const float* __restrict__ bl, int L,
                       int inSel, int outSel, int useRes){
    extern __shared__ float cs[];
    float* WlAT = cs;
    float* WlBT = cs + 4096;
    float* WrST = cs + 8192;
    float* A    = cs + 12288;
    float* B    = cs + 14336;
    float* X    = cs + 16384;
    float* blj  = cs + 18432;
    int v = blockIdx.y;          // 0: source side, 1: target side
    int ia = v ? (L*4+1) : (L*4+0);
    int ib = v ? (L*4+2) : (L*4+3);
    int etA = v ? 1 : 0;
    int etB = v ? 2 : 3;
    int isT = v;
    int tid = threadIdx.x;
    const float* wa = g_WlT + ia*4096;
    const float* wb = g_WlT + ib*4096;
    const float* ra = g_WrT + ia*4096;
    const float* rb = g_WrT + ib*4096;
    for(int i=tid;i<4096;i+=256){
        WlAT[i] = wa[i];
        WlBT[i] = wb[i];
        WrST[i] = ra[i] + rb[i];
    }
    if(tid < 64) blj[tid] = bl[ia*64+tid] + bl[ib*64+tid];
    int nb = blockIdx.x*32;
    const float* xin = isT ? g_tb[inSel] : g_sb[inSel];
    for(int i=tid;i<2048;i+=256){
        int node = nb + (i>>6); int c = i & 63;
        bool ok = node < NN;
        A[i] = ok ? g_agg[etA][node*64+c] : 0.0f;
        B[i] = ok ? g_agg[etB][node*64+c] : 0.0f;
        X[i] = ok ? xin[node*64+c] : 0.0f;
    }
    __syncthreads();
    int j = tid & 63, g = tid >> 6;
    float* out = isT ? g_tb[outSel] : g_sb[outSel];
    #pragma unroll
    for(int mi=0;mi<8;mi++){
        int m = g*8 + mi;
        int node = nb + m;
        float acc = blj[j];
        #pragma unroll 4
        for(int k=0;k<64;k++){
            acc = fmaf(A[m*64+k], WlAT[k*64+j], acc);
            acc = fmaf(B[m*64+k], WlBT[k*64+j], acc);
            acc = fmaf(X[m*64+k], WrST[k*64+j], acc);
        }
        acc *= 0.5f;
        if(useRes) acc += X[m*64+j];
        if(node < NN) out[node*64+j] = fmaxf(acc, 0.0f);
    }
}

// ---- edge head: 32 edges/block, smem k-major weights ----
__global__ void k_edge(const int* __restrict__ edges, const float* __restrict__ ea,
    const float* __restrict__ bg1, const float* __restrict__ Wg2, const float* __restrict__ bg2,
    const float* __restrict__ bm1, const float* __restrict__ bm2, const float* __restrict__ bm3,
    float* __restrict__ out){
    extern __shared__ float es[];
    float* Wg1T = es;               // 8192
    float* Wm1T = es + 8192;        // 5120
    float* Wm2T = es + 13312;       // 2048
    float* Wm3T = es + 15360;       // 64
    float* cvec = es + 15424;       // 256
    float* se   = es + 15680;       // 2048
    float* te   = es + 17728;       // 2048
    float* cat  = es + 19776;       // 2560
    float* h1   = es + 22336;       // 2048
    float* h2   = es + 24384;       // 1024
    float* red  = es + 25408;       // 64
    __shared__ int sidx[32], tidx[32];
    int tid = threadIdx.x;
    for(int i=tid;i<8192;i+=256) Wg1T[i] = g_Wg1T[i];
    for(int i=tid;i<5120;i+=256) Wm1T[i] = g_Wm1T[i];
    for(int i=tid;i<2048;i+=256) Wm2T[i] = g_Wm2T[i];
    if(tid < 64)  Wm3T[tid] = g_Wm3T[tid];
    if(tid < 64)  cvec[tid] = bg1[tid];
    else if(tid < 128) cvec[tid] = Wg2[tid-64];
    else if(tid < 192) cvec[tid] = bm1[tid-128];
    else if(tid < 224) cvec[tid] = bm2[tid-192];
    else if(tid == 224) cvec[224] = bm3[0];
    else if(tid == 225) cvec[225] = bm3[1];
    else if(tid == 226) cvec[226] = bg2[0];
    int ebase = blockIdx.x*32;
    if(tid < 32){
        sidx[tid] = edges[4*EE + ebase + tid];
        tidx[tid] = edges[5*EE + ebase + tid];
    }
    __syncthreads();
    for(int i=tid;i<2048;i+=256){
        int e = i >> 6, c = i & 63;
        se[i] = g_sb[1][sidx[e]*64 + c];
        te[i] = g_tb[1][tidx[e]*64 + c];
    }
    __syncthreads();
    int j = tid & 63, g = tid >> 6;
    int half = (tid >> 5) & 1;
    // Phase A: gate hidden dot Wg2, warp-reduced
    #pragma unroll
    for(int ei=0;ei<8;ei++){
        int e = g*8 + ei;
        float a = cvec[j];
        #pragma unroll 4
        for(int k=0;k<64;k++) a = fmaf(se[e*64+k], Wg1T[k*64+j], a);
        #pragma unroll 4
        for(int k=0;k<64;k++) a = fmaf(te[e*64+k], Wg1T[(64+k)*64+j], a);
        a = fmaxf(a, 0.0f);
        float v = a * cvec[64+j];
        #pragma unroll
        for(int off=16;off>0;off>>=1) v += __shfl_xor_sync(0xffffffffu, v, off);
        if((tid & 31) == 0) red[e*2 + half] = v;
    }
    __syncthreads();
    // Phase B: gate value, er || ea
    #pragma unroll
    for(int ei=0;ei<8;ei++){
        int e = g*8 + ei;
        float gv = sigf(red[e*2] + red[e*2+1] + cvec[226]);
        cat[e*80 + j] = gv*se[e*64+j] + (1.0f-gv)*te[e*64+j];
        if(j < 16) cat[e*80 + 64 + j] = ea[(ebase+e)*16 + j];
    }
    __syncthreads();
    // Phase C: m1
    #pragma unroll
    for(int ei=0;ei<8;ei++){
        int e = g*8 + ei;
        float m = cvec[128+j];
        #pragma unroll 4
        for(int k=0;k<80;k++) m = fmaf(cat[e*80+k], Wm1T[k*64+j], m);
        h1[e*64+j] = fmaxf(m, 0.0f);
    }
    __syncthreads();
    // Phase D: m2 (j<32)
    if(j < 32){
        #pragma unroll
        for(int ei=0;ei<8;ei++){
            int e = g*8 + ei;
            float m = cvec[192+j];
            #pragma unroll 4
            for(int k=0;k<64;k++) m = fmaf(h1[e*64+k], Wm2T[k*32+j], m);
            h2[e*32+j] = fmaxf(m, 0.0f);
        }
    }
    __syncthreads();
    // Phase E: m3 (j<2)
    if(j < 2){
        #pragma unroll
        for(int ei=0;ei<8;ei++){
            int e = g*8 + ei;
            float o = cvec[224+j];
            #pragma unroll
            for(int k=0;k<32;k++) o = fmaf(h2[e*32+k], Wm3T[k*2+j], o);
            out[(ebase+e)*2 + j] = o;
        }
    }
}

// ---------------- host launcher ----------------
extern "C" void kernel_launch(void* const* d_in, const int* in_sizes, int n_in,
                              void* d_out, int out_size){
    const float* x_source = (const float*)d_in[0];
    const float* x_target = (const float*)d_in[1];
    const int*   edges    = (const int*)  d_in[2];
    const float* ea       = (const float*)d_in[3];
    const float* We_s1=(const float*)d_in[4];  const float* be_s1=(const float*)d_in[5];
    const float* We_s2=(const float*)d_in[6];  const float* be_s2=(const float*)d_in[7];
    const float* We_t1=(const float*)d_in[8];  const float* be_t1=(const float*)d_in[9];
    const float* We_t2=(const float*)d_in[10]; const float* be_t2=(const float*)d_in[11];
    const float* Wih=(const float*)d_in[12];   const float* Whh=(const float*)d_in[13];
    const float* bih=(const float*)d_in[14];   const float* bhh=(const float*)d_in[15];
    const float* Wl =(const float*)d_in[16];   const float* bl =(const float*)d_in[17];
    const float* Wr =(const float*)d_in[18];
    const float* Wg1=(const float*)d_in[19];   const float* bg1=(const float*)d_in[20];
    const float* Wg2=(const float*)d_in[21];   const float* bg2=(const float*)d_in[22];
    const float* Wm1=(const float*)d_in[23];   const float* bm1=(const float*)d_in[24];
    const float* Wm2=(const float*)d_in[25];   const float* bm2=(const float*)d_in[26];
    const float* Wm3=(const float*)d_in[27];   const float* bm3=(const float*)d_in[28];
    float* out = (float*)d_out;

    cudaFuncSetAttribute(k_lstm, cudaFuncAttributeMaxDynamicSharedMemorySize, 81920);
    cudaFuncSetAttribute(k_comb, cudaFuncAttributeMaxDynamicSharedMemorySize, 75776);
    cudaFuncSetAttribute(k_edge, cudaFuncAttributeMaxDynamicSharedMemorySize, 102400);

    k_zero    <<<(4*NN+255)/256, 256>>>();
    k_degree  <<<(4*EE+255)/256, 256>>>(edges);
    k_scan    <<<4, 1024>>>();
    k_scatter <<<(4*EE+255)/256, 256>>>(edges);
    k_buildnbr<<<(4*NN+127)/128, 128>>>();
    k_wperm   <<<(2*12*16384 + 12*256 + 255)/256, 256>>>(Whh, Wih, bih, bhh);
    k_prep    <<<(125504+255)/256, 256>>>(Wl, Wr, Wg1, Wm1, Wm2, Wm3, We_s1, We_s2, We_t1, We_t2);
    k_enc     <<<313, 256>>>(x_source, 32, be_s1, be_s2, 0);
    k_enc     <<<313, 256>>>(x_target, 24, be_t1, be_t2, 1);

    for(int L=0; L<3; L++){
        int in = L & 1, o = 1 - in;
        k_U   <<<dim3(157,4), 256>>>(L, in);
        k_lstm<<<dim3(157,4), 256, 81920>>>(L);
        k_comb<<<dim3(313,2), 256, 75776>>>(bl, L, in, o, (L>0)?1:0);
    }
    k_edge<<<1250, 256, 102400>>>(edges, ea, bg1, Wg2, bg2, bm1, bm2, bm3, out);
}